// round 1
// baseline (speedup 1.0000x reference)
#include <cuda_runtime.h>
#include <cuda_bf16.h>
#include <math.h>

// ---------------- problem constants ----------------
#define BB 2
#define SS 4096
#define DD 2048
#define VV 32000
#define HH 16
#define HD 128
#define BSQ 16
#define NA 128
#define MASK_ID 31999
#define DFF 8192
#define NRV (SS - BSQ + 1)          // 4081
#define TT (BB * NA * BSQ)          // 4096 tokens
#define KVT (BB * NA * (BSQ + 1))   // 4352 kv rows
#define NAI (BB * NA)               // 256 anchor slots

// ---------------- scratch (static device globals; no runtime alloc) ----------------
__device__ int   g_anchor[NAI];
__device__ int   g_keep[NAI];
__device__ int   g_first[NAI];
__device__ int   g_ctxpos[NAI];
__device__ float g_x[(size_t)TT * DD];        // residual stream
__device__ float g_kvin[(size_t)KVT * DD];    // normed attn inputs: row0=ctx, rows1..16=hq
__device__ float g_pq[(size_t)KVT * DD];
__device__ float g_pk[(size_t)KVT * DD];
__device__ float g_pv[(size_t)KVT * DD];
__device__ float g_attno[(size_t)TT * DD];
__device__ float g_o[(size_t)TT * DD];        // projection output scratch
__device__ float g_h[(size_t)TT * DD];        // normed scratch
__device__ float g_ff1[(size_t)TT * DFF];
__device__ float g_ff2[(size_t)TT * DFF];
__device__ float g_logits[(size_t)TT * VV];   // 524 MB
__device__ float g_tokl[TT];
__device__ float g_tokw[TT];
__device__ float g_toka[TT];

// ---------------- anchor selection (exact argsort-stable semantics) ----------------
__global__ void k_select(const float* __restrict__ rand_vals,
                         const float* __restrict__ loss_mask,
                         const int*   __restrict__ input_ids) {
    int b = blockIdx.x;
    __shared__ float srv[NRV];
    __shared__ unsigned char sel[NRV];
    const float* rv = rand_vals + (size_t)b * NRV;
    const float* lm = loss_mask + (size_t)b * SS;
    for (int i = threadIdx.x; i < NRV; i += blockDim.x)
        srv[i] = (lm[i] > 0.5f) ? rv[i] : 2.0f;
    __syncthreads();
    for (int i = threadIdx.x; i < NRV; i += blockDim.x) {
        float vi = srv[i];
        int r = 0;
        for (int j = 0; j < NRV; j++) {
            float vj = srv[j];
            r += (vj < vi) || (vj == vi && j < i);
        }
        sel[i] = (r < NA && vi < 1.5f) ? 1 : 0;   // valid <=> srv < 1.5 (invalid forced to 2.0)
    }
    __syncthreads();
    if (threadIdx.x == 0) {
        int slot = 0;
        int tmp[NA];
        for (int i = 0; i < NRV && slot < NA; i++)
            if (sel[i]) tmp[slot++] = i;
        for (int s = 0; s < NA; s++) {
            int kp = (s < slot) ? 1 : 0;
            int a  = kp ? tmp[s] : 0;
            int ai = b * NA + s;
            g_anchor[ai] = a;
            g_keep[ai]   = kp;
            int clipped = a < (SS - 1) ? a : (SS - 1);
            int tok = input_ids[(size_t)b * SS + clipped];
            g_first[ai]  = kp ? tok : MASK_ID;
            g_ctxpos[ai] = (a - 1 > 0) ? (a - 1) : 0;
        }
    }
}

// ---------------- embedding gather ----------------
__global__ void k_embed(const float* __restrict__ emb) {
    int t  = blockIdx.x;          // token
    int j  = t & 15;
    int ai = t >> 4;
    int id = (j == 0) ? g_first[ai] : MASK_ID;
    const float4* src = (const float4*)(emb + (size_t)id * DD);
    float4* dst = (float4*)(g_x + (size_t)t * DD);
    for (int i = threadIdx.x; i < DD / 4; i += blockDim.x) dst[i] = src[i];
}

// ---------------- rmsnorm helpers ----------------
__device__ __forceinline__ float blk_sum(float v, float* sh) {
    int tid = threadIdx.x;
    sh[tid] = v; __syncthreads();
    for (int s = blockDim.x / 2; s > 0; s >>= 1) {
        if (tid < s) sh[tid] += sh[tid + s];
        __syncthreads();
    }
    return sh[0];
}

__device__ __forceinline__ void rms_row(const float* __restrict__ in,
                                        float* __restrict__ out,
                                        const float* __restrict__ w,
                                        float* sh) {
    float ss = 0.f;
    for (int c = threadIdx.x; c < DD; c += blockDim.x) { float v = in[c]; ss += v * v; }
    ss = blk_sum(ss, sh);
    float scale = rsqrtf(ss / (float)DD + 1e-6f);
    for (int c = threadIdx.x; c < DD; c += blockDim.x) out[c] = in[c] * scale * w[c];
}

// hq rows: x tokens -> kvin rows 1..16
__global__ void k_rms_hq(const float* __restrict__ w) {
    __shared__ float sh[256];
    int t = blockIdx.x;
    int j = t & 15, ai = t >> 4;
    rms_row(g_x + (size_t)t * DD, g_kvin + (size_t)(ai * 17 + 1 + j) * DD, w, sh);
}
// ctx rows: hidden_states[ctxpos] -> kvin row 0
__global__ void k_rms_hc(const float* __restrict__ hs, const float* __restrict__ w) {
    __shared__ float sh[256];
    int r = blockIdx.x;              // 0..255 anchor slot
    int b = r / NA;
    rms_row(hs + ((size_t)b * SS + g_ctxpos[r]) * DD, g_kvin + (size_t)(r * 17) * DD, w, sh);
}
// contiguous token rows
__global__ void k_rms_tok(const float* __restrict__ in, float* __restrict__ out,
                          const float* __restrict__ w) {
    __shared__ float sh[256];
    int t = blockIdx.x;
    rms_row(in + (size_t)t * DD, out + (size_t)t * DD, w, sh);
}

// ---------------- tiled fp32 GEMM: C[M,N] = A[M,K] @ op(B) ----------------
// TRANSB=false: B is K x N row-major.  TRANSB=true: B is N x K row-major (B^T used).
template<bool TRANSB>
__global__ void __launch_bounds__(256, 2)
k_gemm(const float* __restrict__ A, const float* __restrict__ B,
       float* __restrict__ C, int M, int N, int K) {
    const int BM = 128, BN = 128, BK = 16;
    __shared__ float As[BK][BM + 4];
    __shared__ float Bs[BK][BN + 4];
    int tid = threadIdx.x;
    int tx = tid & 15, ty = tid >> 4;
    int m0 = blockIdx.y * BM, n0 = blockIdx.x * BN;
    float acc[8][8];
#pragma unroll
    for (int i = 0; i < 8; i++)
#pragma unroll
        for (int j = 0; j < 8; j++) acc[i][j] = 0.f;

    for (int k0 = 0; k0 < K; k0 += BK) {
        // A tile: 128 rows x 16 cols
        {
            int r = tid >> 2, c = (tid & 3) * 4;
#pragma unroll
            for (int it = 0; it < 2; it++) {
                float4 v = *(const float4*)(A + (size_t)(m0 + r + it * 64) * K + k0 + c);
                As[c + 0][r + it * 64] = v.x;
                As[c + 1][r + it * 64] = v.y;
                As[c + 2][r + it * 64] = v.z;
                As[c + 3][r + it * 64] = v.w;
            }
        }
        if (!TRANSB) {
            int kr = tid >> 5, c = (tid & 31) * 4;
#pragma unroll
            for (int it = 0; it < 2; it++) {
                float4 v = *(const float4*)(B + (size_t)(k0 + kr + it * 8) * N + n0 + c);
                *(float4*)&Bs[kr + it * 8][c] = v;
            }
        } else {
            int r = tid >> 2, c = (tid & 3) * 4;
#pragma unroll
            for (int it = 0; it < 2; it++) {
                float4 v = *(const float4*)(B + (size_t)(n0 + r + it * 64) * K + k0 + c);
                Bs[c + 0][r + it * 64] = v.x;
                Bs[c + 1][r + it * 64] = v.y;
                Bs[c + 2][r + it * 64] = v.z;
                Bs[c + 3][r + it * 64] = v.w;
            }
        }
        __syncthreads();
#pragma unroll
        for (int k = 0; k < BK; k++) {
            float ra[8], rb[8];
#pragma unroll
            for (int i = 0; i < 8; i++) ra[i] = As[k][ty * 8 + i];
#pragma unroll
            for (int j = 0; j < 8; j++) rb[j] = Bs[k][tx * 8 + j];
#pragma unroll
            for (int i = 0; i < 8; i++)
#pragma unroll
                for (int j = 0; j < 8; j++) acc[i][j] += ra[i] * rb[j];
        }
        __syncthreads();
    }
#pragma unroll
    for (int i = 0; i < 8; i++) {
        float* cp = C + (size_t)(m0 + ty * 8 + i) * N + n0 + tx * 8;
        *(float4*)(cp)     = make_float4(acc[i][0], acc[i][1], acc[i][2], acc[i][3]);
        *(float4*)(cp + 4) = make_float4(acc[i][4], acc[i][5], acc[i][6], acc[i][7]);
    }
}

// ---------------- rope (in-place on g_pq / g_pk) ----------------
__global__ void k_rope() {
    int r  = blockIdx.x;       // kv row 0..4351
    int kk = r % 17;
    int ai = r / 17;
    int pos = (kk == 0) ? g_ctxpos[ai] : (g_anchor[ai] + kk - 1);
    float* kr = g_pk + (size_t)r * DD;
    float* qr = g_pq + (size_t)r * DD;
    for (int p = threadIdx.x; p < HH * 64; p += blockDim.x) {
        int h = p >> 6, d = p & 63;
        float inv = expf(-(float)d * 0.14391156965722198f);   // ln(10000)/64
        float ang = (float)pos * inv;
        float s, c;
        sincosf(ang, &s, &c);
        int c1 = h * HD + d, c2 = c1 + 64;
        float x1 = kr[c1], x2 = kr[c2];
        kr[c1] = x1 * c - x2 * s;
        kr[c2] = x2 * c + x1 * s;
        if (kk > 0) {
            float y1 = qr[c1], y2 = qr[c2];
            qr[c1] = y1 * c - y2 * s;
            qr[c2] = y2 * c + y1 * s;
        }
    }
}

// ---------------- attention: per (b, anchor, head) block ----------------
__global__ void __launch_bounds__(288) k_attn() {
    int g = blockIdx.x;
    int h  = g & 15;
    int na = (g >> 4) & 127;
    int b  = g >> 11;
    int base = (b * NA + na) * 17;
    __shared__ float sk[17][HD], sv[17][HD], sq[BSQ][HD], sw[BSQ][18];
    int tid = threadIdx.x;
    for (int i = tid; i < 17 * HD; i += 288) {
        int r = i >> 7, c = i & 127;
        size_t off = (size_t)(base + r) * DD + h * HD + c;
        sk[r][c] = g_pk[off];
        sv[r][c] = g_pv[off];
    }
    for (int i = tid; i < BSQ * HD; i += 288) {
        int r = i >> 7, c = i & 127;
        sq[r][c] = g_pq[(size_t)(base + 1 + r) * DD + h * HD + c];
    }
    __syncthreads();
    if (tid < BSQ * 17) {
        int j = tid / 17, kk = tid % 17;
        float d = 0.f;
#pragma unroll 8
        for (int c = 0; c < HD; c++) d += sq[j][c] * sk[kk][c];
        sw[j][kk] = d * 0.08838834764831845f;   // 1/sqrt(128)
    }
    __syncthreads();
    if (tid < BSQ) {
        float m = -3.4e38f;
        for (int kk = 0; kk < 17; kk++) m = fmaxf(m, sw[tid][kk]);
        float s = 0.f;
        for (int kk = 0; kk < 17; kk++) { float e = expf(sw[tid][kk] - m); sw[tid][kk] = e; s += e; }
        float invs = 1.f / s;
        for (int kk = 0; kk < 17; kk++) sw[tid][kk] *= invs;
    }
    __syncthreads();
    for (int i = tid; i < BSQ * HD; i += 288) {
        int j = i >> 7, c = i & 127;
        float o = 0.f;
#pragma unroll
        for (int kk = 0; kk < 17; kk++) o += sw[j][kk] * sv[kk][c];
        g_attno[(size_t)(b * 2048 + na * BSQ + j) * DD + h * HD + c] = o;
    }
}

// ---------------- residual adds ----------------
__global__ void k_resid(float* __restrict__ x, const float* __restrict__ o, int useKeep) {
    int t = blockIdx.x;
    float m = 1.f;
    if (useKeep) m = (float)g_keep[t >> 4];
    size_t off = (size_t)t * DD;
    for (int c = threadIdx.x; c < DD; c += blockDim.x) x[off + c] += m * o[off + c];
}

// ---------------- swiglu ----------------
__global__ void k_swiglu(float* __restrict__ gte, const float* __restrict__ up, size_t n) {
    for (size_t i = (size_t)blockIdx.x * blockDim.x + threadIdx.x; i < n;
         i += (size_t)gridDim.x * blockDim.x) {
        float x = gte[i];
        float s = x / (1.f + expf(-x));
        gte[i] = s * up[i];
    }
}

// ---------------- per-token cross-entropy / argmax ----------------
__global__ void k_loss(const int* __restrict__ input_ids, const float* __restrict__ loss_mask) {
    int t = blockIdx.x;
    const float* row = g_logits + (size_t)t * VV;
    int tid = threadIdx.x;
    __shared__ float smax[256];
    __shared__ int   sidx[256];
    __shared__ float ssum[256];
    float lm = -3.4e38f; int li = 0;
    for (int i = tid; i < VV; i += 256) {
        float v = row[i];
        if (v > lm) { lm = v; li = i; }
    }
    smax[tid] = lm; sidx[tid] = li; __syncthreads();
    for (int s = 128; s > 0; s >>= 1) {
        if (tid < s) {
            float v2 = smax[tid + s]; int i2 = sidx[tid + s];
            if (v2 > smax[tid] || (v2 == smax[tid] && i2 < sidx[tid])) {
                smax[tid] = v2; sidx[tid] = i2;
            }
        }
        __syncthreads();
    }
    float m = smax[0];
    int pred = sidx[0];
    float s = 0.f;
    for (int i = tid; i < VV; i += 256) s += expf(row[i] - m);
    ssum[tid] = s; __syncthreads();
    for (int st = 128; st > 0; st >>= 1) {
        if (tid < st) ssum[tid] += ssum[tid + st];
        __syncthreads();
    }
    if (tid == 0) {
        float logZ = m + logf(ssum[0]);
        int j = t & 15, ai = t >> 4, b = t >> 11;
        int anc = g_anchor[ai];
        int label = anc + j;
        int vl = label < SS;
        int safe = label < (SS - 1) ? label : (SS - 1);
        int tgt = input_ids[(size_t)b * SS + safe];
        float lmg = loss_mask[(size_t)b * SS + safe];
        float w = (g_keep[ai] && vl && j > 0) ? lmg : 0.f;
        float lp = row[tgt] - logZ;
        g_tokl[t] = w * (-lp);
        g_tokw[t] = w;
        g_toka[t] = (pred == tgt && w > 0.5f) ? 1.f : 0.f;
    }
}

__global__ void k_final(float* __restrict__ out) {
    __shared__ float s1[256], s2[256], s3[256];
    int tid = threadIdx.x;
    float a = 0.f, b = 0.f, c = 0.f;
    for (int t = tid; t < TT; t += 256) { a += g_tokl[t]; b += g_tokw[t]; c += g_toka[t]; }
    s1[tid] = a; s2[tid] = b; s3[tid] = c; __syncthreads();
    for (int s = 128; s > 0; s >>= 1) {
        if (tid < s) { s1[tid] += s1[tid + s]; s2[tid] += s2[tid + s]; s3[tid] += s3[tid + s]; }
        __syncthreads();
    }
    if (tid == 0) {
        float denom = s2[0] + 1e-6f;
        out[0] = s1[0] / denom;
        out[1] = s3[0] / denom;
    }
}

// ---------------- driver ----------------
extern "C" void kernel_launch(void* const* d_in, const int* in_sizes, int n_in,
                              void* d_out, int out_size) {
    const int*   input_ids     = (const int*)  d_in[0];
    const float* hidden_states = (const float*)d_in[1];
    const float* loss_mask     = (const float*)d_in[2];
    const float* rand_vals     = (const float*)d_in[3];
    const float* embed_table   = (const float*)d_in[4];
    const float* lm_head_w     = (const float*)d_in[5];
    const float* wq            = (const float*)d_in[6];
    const float* wk            = (const float*)d_in[7];
    const float* wv            = (const float*)d_in[8];
    const float* wo            = (const float*)d_in[9];
    const float* w_gate        = (const float*)d_in[10];
    const float* w_up          = (const float*)d_in[11];
    const float* w_down        = (const float*)d_in[12];
    const float* norm_attn     = (const float*)d_in[13];
    const float* norm_mlp      = (const float*)d_in[14];
    const float* norm_out      = (const float*)d_in[15];
    const float* norm_chs      = (const float*)d_in[16];
    float* out = (float*)d_out;

    float *px, *pkvin, *ppq, *ppk, *ppv, *pattno, *po, *ph, *pff1, *pff2, *plog;
    cudaGetSymbolAddress((void**)&px,     g_x);
    cudaGetSymbolAddress((void**)&pkvin,  g_kvin);
    cudaGetSymbolAddress((void**)&ppq,    g_pq);
    cudaGetSymbolAddress((void**)&ppk,    g_pk);
    cudaGetSymbolAddress((void**)&ppv,    g_pv);
    cudaGetSymbolAddress((void**)&pattno, g_attno);
    cudaGetSymbolAddress((void**)&po,     g_o);
    cudaGetSymbolAddress((void**)&ph,     g_h);
    cudaGetSymbolAddress((void**)&pff1,   g_ff1);
    cudaGetSymbolAddress((void**)&pff2,   g_ff2);
    cudaGetSymbolAddress((void**)&plog,   g_logits);

    // 1) anchor selection
    k_select<<<BB, 256>>>(rand_vals, loss_mask, input_ids);
    // 2) embeddings -> residual stream
    k_embed<<<TT, 256>>>(embed_table);
    // 3) rmsnorms into kv input matrix
    k_rms_hq<<<TT, 256>>>(norm_attn);
    k_rms_hc<<<NAI, 256>>>(hidden_states, norm_chs);
    // 4) qkv projections (M=4352, N=2048, K=2048)
    {
        dim3 g(DD / 128, KVT / 128);
        k_gemm<false><<<g, 256>>>(pkvin, wq, ppq, KVT, DD, DD);
        k_gemm<false><<<g, 256>>>(pkvin, wk, ppk, KVT, DD, DD);
        k_gemm<false><<<g, 256>>>(pkvin, wv, ppv, KVT, DD, DD);
    }
    // 5) rope
    k_rope<<<KVT, 256>>>();
    // 6) attention
    k_attn<<<TT, 288>>>();
    // 7) output projection + masked residual
    {
        dim3 g(DD / 128, TT / 128);
        k_gemm<false><<<g, 256>>>(pattno, wo, po, TT, DD, DD);
    }
    k_resid<<<TT, 256>>>(px, po, 1);
    // 8) MLP
    k_rms_tok<<<TT, 256>>>(px, ph, norm_mlp);
    {
        dim3 g(DFF / 128, TT / 128);
        k_gemm<false><<<g, 256>>>(ph, w_gate, pff1, TT, DFF, DD);
        k_gemm<false><<<g, 256>>>(ph, w_up,   pff2, TT, DFF, DD);
    }
    k_swiglu<<<8192, 256>>>(pff1, pff2, (size_t)TT * DFF);
    {
        dim3 g(DD / 128, TT / 128);
        k_gemm<false><<<g, 256>>>(pff1, w_down, po, TT, DD, DFF);
    }
    k_resid<<<TT, 256>>>(px, po, 0);
    // 9) output norm + lm head (B transposed: lm_head_w is V x D)
    k_rms_tok<<<TT, 256>>>(px, ph, norm_out);
    {
        dim3 g(VV / 128, TT / 128);
        k_gemm<true><<<g, 256>>>(ph, lm_head_w, plog, TT, VV, DD);
    }
    // 10) loss + accuracy (deterministic two-stage reduction)
    k_loss<<<TT, 256>>>(input_ids, loss_mask);
    k_final<<<1, 256>>>(out);
}

// round 3
// speedup vs baseline: 4.9893x; 4.9893x over previous
#include <cuda_runtime.h>
#include <cuda_bf16.h>
#include <math.h>
#include <stdint.h>

// ---------------- problem constants ----------------
#define BB 2
#define SS 4096
#define DD 2048
#define VV 32000
#define HH 16
#define HD 128
#define BSQ 16
#define NA 128
#define MASK_ID 31999
#define DFF 8192
#define NRV (SS - BSQ + 1)          // 4081
#define TT (BB * NA * BSQ)          // 4096 tokens
#define KVT (BB * NA * (BSQ + 1))   // 4352 kv rows
#define NAI (BB * NA)               // 256 anchor slots

// ---------------- scratch ----------------
__device__ int   g_anchor[NAI];
__device__ int   g_keep[NAI];
__device__ int   g_first[NAI];
__device__ int   g_ctxpos[NAI];
__device__ unsigned char g_sel[BB * 4096];

__device__ float g_x[(size_t)TT * DD];
__device__ float g_pq[(size_t)KVT * DD];
__device__ float g_pk[(size_t)KVT * DD];
__device__ float g_pv[(size_t)KVT * DD];
__device__ float g_o[(size_t)TT * DD];
__device__ float g_ff1[(size_t)TT * DFF];
__device__ float g_ff2[(size_t)TT * DFF];
__device__ float g_logits[(size_t)TT * VV];
__device__ float g_tokl[TT];
__device__ float g_tokw[TT];
__device__ float g_toka[TT];

__device__ __nv_bfloat16 g_kvin_bf[(size_t)KVT * DD];
__device__ __nv_bfloat16 g_attno_bf[(size_t)TT * DD];
__device__ __nv_bfloat16 g_h_bf[(size_t)TT * DD];
__device__ __nv_bfloat16 g_ff1p_bf[(size_t)TT * DFF];
__device__ __nv_bfloat16 g_wqT[(size_t)DD * DD];
__device__ __nv_bfloat16 g_wkT[(size_t)DD * DD];
__device__ __nv_bfloat16 g_wvT[(size_t)DD * DD];
__device__ __nv_bfloat16 g_woT[(size_t)DD * DD];
__device__ __nv_bfloat16 g_wgT[(size_t)DFF * DD];
__device__ __nv_bfloat16 g_wuT[(size_t)DFF * DD];
__device__ __nv_bfloat16 g_wdT[(size_t)DD * DFF];
__device__ __nv_bfloat16 g_lmb[(size_t)VV * DD];

// ---------------- helpers ----------------
__device__ __forceinline__ uint32_t smem_u32(const void* p) {
    uint32_t a;
    asm("{ .reg .u64 t; cvta.to.shared.u64 t, %1; cvt.u32.u64 %0, t; }" : "=r"(a) : "l"(p));
    return a;
}
__device__ __forceinline__ void cpa16(uint32_t dst, const void* src) {
    asm volatile("cp.async.cg.shared.global [%0], [%1], 16;" :: "r"(dst), "l"(src));
}
#define CP_COMMIT() asm volatile("cp.async.commit_group;" ::: "memory")
#define CP_WAIT1()  asm volatile("cp.async.wait_group 1;" ::: "memory")

__device__ __forceinline__ void ldsm4(uint32_t& r0, uint32_t& r1, uint32_t& r2, uint32_t& r3,
                                      uint32_t addr) {
    asm volatile("ldmatrix.sync.aligned.m8n8.x4.shared.b16 {%0,%1,%2,%3}, [%4];"
                 : "=r"(r0), "=r"(r1), "=r"(r2), "=r"(r3) : "r"(addr));
}
__device__ __forceinline__ void mma16816(float* c, const uint32_t* a, const uint32_t* b) {
    asm volatile("mma.sync.aligned.m16n8k16.row.col.f32.bf16.bf16.f32 "
                 "{%0,%1,%2,%3}, {%4,%5,%6,%7}, {%8,%9}, {%0,%1,%2,%3};"
                 : "+f"(c[0]), "+f"(c[1]), "+f"(c[2]), "+f"(c[3])
                 : "r"(a[0]), "r"(a[1]), "r"(a[2]), "r"(a[3]), "r"(b[0]), "r"(b[1]));
}

// ---------------- anchor selection ----------------
__global__ void k_rank(const float* __restrict__ rand_vals,
                       const float* __restrict__ loss_mask) {
    int b = blockIdx.y;
    __shared__ float srv[NRV];
    const float* rv = rand_vals + (size_t)b * NRV;
    const float* lm = loss_mask + (size_t)b * SS;
    for (int i = threadIdx.x; i < NRV; i += blockDim.x)
        srv[i] = (lm[i] > 0.5f) ? rv[i] : 2.0f;
    __syncthreads();
    int i = blockIdx.x * 256 + threadIdx.x;
    if (i < NRV) {
        float vi = srv[i];
        int r = 0;
        for (int j = 0; j < NRV; j++) {
            float vj = srv[j];
            r += (vj < vi) || (vj == vi && j < i);
        }
        g_sel[b * 4096 + i] = (r < NA && vi < 1.5f) ? 1 : 0;
    }
}

__global__ void k_compact(const int* __restrict__ input_ids) {
    int b = blockIdx.x;
    __shared__ unsigned char s[NRV];
    for (int i = threadIdx.x; i < NRV; i += blockDim.x) s[i] = g_sel[b * 4096 + i];
    __syncthreads();
    if (threadIdx.x == 0) {
        int slot = 0;
        int tmp[NA];
        for (int i = 0; i < NRV && slot < NA; i++)
            if (s[i]) tmp[slot++] = i;
        for (int k = 0; k < NA; k++) {
            int kp = (k < slot) ? 1 : 0;
            int a  = kp ? tmp[k] : 0;
            int ai = b * NA + k;
            g_anchor[ai] = a;
            g_keep[ai]   = kp;
            int clipped = a < (SS - 1) ? a : (SS - 1);
            g_first[ai]  = kp ? input_ids[(size_t)b * SS + clipped] : MASK_ID;
            g_ctxpos[ai] = (a - 1 > 0) ? (a - 1) : 0;
        }
    }
}

// ---------------- embedding ----------------
__global__ void k_embed(const float* __restrict__ emb) {
    int t  = blockIdx.x;
    int j  = t & 15;
    int ai = t >> 4;
    int id = (j == 0) ? g_first[ai] : MASK_ID;
    const float4* src = (const float4*)(emb + (size_t)id * DD);
    float4* dst = (float4*)(g_x + (size_t)t * DD);
    for (int i = threadIdx.x; i < DD / 4; i += blockDim.x) dst[i] = src[i];
}

// ---------------- rmsnorm -> bf16 ----------------
__device__ __forceinline__ float blk_sum(float v, float* sh) {
    int tid = threadIdx.x;
    sh[tid] = v; __syncthreads();
    for (int s = blockDim.x / 2; s > 0; s >>= 1) {
        if (tid < s) sh[tid] += sh[tid + s];
        __syncthreads();
    }
    return sh[0];
}
__device__ __forceinline__ void rms_row_bf(const float* __restrict__ in,
                                           __nv_bfloat16* __restrict__ out,
                                           const float* __restrict__ w, float* sh) {
    float ss = 0.f;
    for (int c = threadIdx.x; c < DD; c += blockDim.x) { float v = in[c]; ss += v * v; }
    ss = blk_sum(ss, sh);
    float scale = rsqrtf(ss / (float)DD + 1e-6f);
    for (int c = threadIdx.x; c < DD; c += blockDim.x)
        out[c] = __float2bfloat16(in[c] * scale * w[c]);
}
__global__ void k_rms_hq(const float* __restrict__ w) {
    __shared__ float sh[256];
    int t = blockIdx.x;
    int j = t & 15, ai = t >> 4;
    rms_row_bf(g_x + (size_t)t * DD, g_kvin_bf + (size_t)(ai * 17 + 1 + j) * DD, w, sh);
}
__global__ void k_rms_hc(const float* __restrict__ hs, const float* __restrict__ w) {
    __shared__ float sh[256];
    int r = blockIdx.x;
    int b = r / NA;
    rms_row_bf(hs + ((size_t)b * SS + g_ctxpos[r]) * DD, g_kvin_bf + (size_t)(r * 17) * DD, w, sh);
}
__global__ void k_rms_tok_bf(const float* __restrict__ in, __nv_bfloat16* __restrict__ out,
                             const float* __restrict__ w) {
    __shared__ float sh[256];
    int t = blockIdx.x;
    rms_row_bf(in + (size_t)t * DD, out + (size_t)t * DD, w, sh);
}

// ---------------- weight prep ----------------
__global__ void k_convT(const float* __restrict__ W, __nv_bfloat16* __restrict__ Wt,
                        int K, int N) {
    __shared__ float t[32][33];
    int n0 = blockIdx.x * 32, k0 = blockIdx.y * 32;
    int tx = threadIdx.x, ty = threadIdx.y;
#pragma unroll
    for (int j = 0; j < 32; j += 8)
        t[ty + j][tx] = W[(size_t)(k0 + ty + j) * N + n0 + tx];
    __syncthreads();
#pragma unroll
    for (int j = 0; j < 32; j += 8)
        Wt[(size_t)(n0 + ty + j) * K + k0 + tx] = __float2bfloat16(t[tx][ty + j]);
}
__global__ void k_conv(const float* __restrict__ in, __nv_bfloat16* __restrict__ out, size_t n) {
    for (size_t i = (size_t)blockIdx.x * blockDim.x + threadIdx.x; i < n;
         i += (size_t)gridDim.x * blockDim.x)
        out[i] = __float2bfloat16(in[i]);
}

// ---------------- bf16 mma.sync GEMM: C[M,N] = A[M,K] @ Bt[N,K]^T ----------------
// block 128x128x32, 256 thr (8 warps 4x2), warp 32x64, 3-stage cp.async
#define GSTG 3
#define ROWB 80                       // smem row stride bytes (32 bf16 + 8 pad)
#define OPB  (128 * ROWB)             // 10240 per operand per stage
#define STGB (2 * OPB)                // 20480
#define GSMEM (GSTG * STGB)           // 61440

__device__ __forceinline__ void g_load_stage(uint32_t st, const __nv_bfloat16* Ab,
                                             const __nv_bfloat16* Bb, int K, int kb, int tid) {
#pragma unroll
    for (int i = 0; i < 2; i++) {
        int id = tid + i * 256;
        int r = id >> 2, ch = id & 3;
        const __nv_bfloat16* as = Ab + (size_t)r * K + kb * 32 + ch * 8;
        const __nv_bfloat16* bs = Bb + (size_t)r * K + kb * 32 + ch * 8;
        cpa16(st + r * ROWB + ch * 16, as);
        cpa16(st + OPB + r * ROWB + ch * 16, bs);
    }
}

__global__ void __launch_bounds__(256, 1)
k_tgemm(const __nv_bfloat16* __restrict__ A, const __nv_bfloat16* __restrict__ Bt,
        float* __restrict__ C, int M, int N, int K) {
    extern __shared__ char smem[];
    uint32_t sb = smem_u32(smem);
    int tid = threadIdx.x;
    int lane = tid & 31, w = tid >> 5;
    int wm = w >> 1, wn = w & 1;
    int m0 = blockIdx.x * 128, n0 = blockIdx.y * 128;
    const __nv_bfloat16* Ab = A + (size_t)m0 * K;
    const __nv_bfloat16* Bb = Bt + (size_t)n0 * K;

    float acc[2][8][4];
#pragma unroll
    for (int i = 0; i < 2; i++)
#pragma unroll
        for (int j = 0; j < 8; j++)
#pragma unroll
            for (int q = 0; q < 4; q++) acc[i][j][q] = 0.f;

    int nk = K >> 5;
    // prologue
#pragma unroll
    for (int s = 0; s < GSTG - 1; s++) {
        g_load_stage(sb + s * STGB, Ab, Bb, K, s, tid);
        CP_COMMIT();
    }

    // precomputed intra-warp frag address offsets
    uint32_t aoff = (uint32_t)((wm * 32 + (lane & 15)) * ROWB + (lane >> 4) * 16);
    uint32_t boff = (uint32_t)(OPB + (wn * 64 + (lane & 7) + ((lane >> 4) & 1) * 8) * ROWB +
                               ((lane >> 3) & 1) * 16);

    for (int kb = 0; kb < nk; kb++) {
        uint32_t st = sb + (kb % GSTG) * STGB;
        CP_WAIT1();
        __syncthreads();

        uint32_t a0[2][4], b0[4][4];   // ks=0 frags
        uint32_t a1[2][4], b1[4][4];   // ks=1 frags
#pragma unroll
        for (int mt = 0; mt < 2; mt++) {
            ldsm4(a0[mt][0], a0[mt][1], a0[mt][2], a0[mt][3], st + aoff + mt * 16 * ROWB);
            ldsm4(a1[mt][0], a1[mt][1], a1[mt][2], a1[mt][3], st + aoff + mt * 16 * ROWB + 32);
        }
#pragma unroll
        for (int p = 0; p < 4; p++) {
            ldsm4(b0[p][0], b0[p][1], b0[p][2], b0[p][3], st + boff + p * 16 * ROWB);
            ldsm4(b1[p][0], b1[p][1], b1[p][2], b1[p][3], st + boff + p * 16 * ROWB + 32);
        }
        __syncthreads();
        if (kb + GSTG - 1 < nk)
            g_load_stage(sb + ((kb + GSTG - 1) % GSTG) * STGB, Ab, Bb, K, kb + GSTG - 1, tid);
        CP_COMMIT();

#pragma unroll
        for (int mt = 0; mt < 2; mt++)
#pragma unroll
            for (int p = 0; p < 4; p++) {
                mma16816(acc[mt][2 * p],     a0[mt], &b0[p][0]);
                mma16816(acc[mt][2 * p + 1], a0[mt], &b0[p][2]);
                mma16816(acc[mt][2 * p],     a1[mt], &b1[p][0]);
                mma16816(acc[mt][2 * p + 1], a1[mt], &b1[p][2]);
            }
    }

    // epilogue
#pragma unroll
    for (int mt = 0; mt < 2; mt++) {
        int r0 = m0 + wm * 32 + mt * 16 + (lane >> 2);
#pragma unroll
        for (int nt = 0; nt < 8; nt++) {
            int c = n0 + wn * 64 + nt * 8 + (lane & 3) * 2;
            *(float2*)(C + (size_t)r0 * N + c)       = make_float2(acc[mt][nt][0], acc[mt][nt][1]);
            *(float2*)(C + (size_t)(r0 + 8) * N + c) = make_float2(acc[mt][nt][2], acc[mt][nt][3]);
        }
    }
}

// ---------------- rope ----------------
__global__ void k_rope() {
    int r  = blockIdx.x;
    int kk = r % 17;
    int ai = r / 17;
    int pos = (kk == 0) ? g_ctxpos[ai] : (g_anchor[ai] + kk - 1);
    float* kr = g_pk + (size_t)r * DD;
    float* qr = g_pq + (size_t)r * DD;
    for (int p = threadIdx.x; p < HH * 64; p += blockDim.x) {
        int h = p >> 6, d = p & 63;
        float inv = expf(-(float)d * 0.14391156965722198f);
        float ang = (float)pos * inv;
        float s, c;
        sincosf(ang, &s, &c);
        int c1 = h * HD + d, c2 = c1 + 64;
        float x1 = kr[c1], x2 = kr[c2];
        kr[c1] = x1 * c - x2 * s;
        kr[c2] = x2 * c + x1 * s;
        if (kk > 0) {
            float y1 = qr[c1], y2 = qr[c2];
            qr[c1] = y1 * c - y2 * s;
            qr[c2] = y2 * c + y1 * s;
        }
    }
}

// ---------------- attention ----------------
__global__ void __launch_bounds__(288) k_attn() {
    int g = blockIdx.x;
    int h  = g & 15;
    int na = (g >> 4) & 127;
    int b  = g >> 11;
    int base = (b * NA + na) * 17;
    __shared__ float sk[17][HD], sv[17][HD], sq[BSQ][HD], sw[BSQ][18];
    int tid = threadIdx.x;
    for (int i = tid; i < 17 * HD; i += 288) {
        int r = i >> 7, c = i & 127;
        size_t off = (size_t)(base + r) * DD + h * HD + c;
        sk[r][c] = g_pk[off];
        sv[r][c] = g_pv[off];
    }
    for (int i = tid; i < BSQ * HD; i += 288) {
        int r = i >> 7, c = i & 127;
        sq[r][c] = g_pq[(size_t)(base + 1 + r) * DD + h * HD + c];
    }
    __syncthreads();
    if (tid < BSQ * 17) {
        int j = tid / 17, kk = tid % 17;
        float d = 0.f;
#pragma unroll 8
        for (int c = 0; c < HD; c++) d += sq[j][c] * sk[kk][c];
        sw[j][kk] = d * 0.08838834764831845f;
    }
    __syncthreads();
    if (tid < BSQ) {
        float m = -3.4e38f;
        for (int kk = 0; kk < 17; kk++) m = fmaxf(m, sw[tid][kk]);
        float s = 0.f;
        for (int kk = 0; kk < 17; kk++) { float e = expf(sw[tid][kk] - m); sw[tid][kk] = e; s += e; }
        float invs = 1.f / s;
        for (int kk = 0; kk < 17; kk++) sw[tid][kk] *= invs;
    }
    __syncthreads();
    for (int i = tid; i < BSQ * HD; i += 288) {
        int j = i >> 7, c = i & 127;
        float o = 0.f;
#pragma unroll
        for (int kk = 0; kk < 17; kk++) o += sw[j][kk] * sv[kk][c];
        g_attno_bf[(size_t)(b * 2048 + na * BSQ + j) * DD + h * HD + c] = __float2bfloat16(o);
    }
}

// ---------------- residual / swiglu ----------------
__global__ void k_resid(float* __restrict__ x, const float* __restrict__ o, int useKeep) {
    int t = blockIdx.x;
    float m = 1.f;
    if (useKeep) m = (float)g_keep[t >> 4];
    size_t off = (size_t)t * DD;
    for (int c = threadIdx.x; c < DD; c += blockDim.x) x[off + c] += m * o[off + c];
}
__global__ void k_swiglu(const float* __restrict__ gte, const float* __restrict__ up,
                         __nv_bfloat16* __restrict__ out, size_t n) {
    for (size_t i = (size_t)blockIdx.x * blockDim.x + threadIdx.x; i < n;
         i += (size_t)gridDim.x * blockDim.x) {
        float x = gte[i];
        float s = x / (1.f + expf(-x));
        out[i] = __float2bfloat16(s * up[i]);
    }
}

// ---------------- fused CE loss / argmax ----------------
__global__ void k_loss(const int* __restrict__ input_ids, const float* __restrict__ loss_mask) {
    int t = blockIdx.x;
    const float* row = g_logits + (size_t)t * VV;
    int tid = threadIdx.x;
    __shared__ float smx[256]; __shared__ float ssm[256]; __shared__ int sid[256];
    float m = -3.4e38f, s = 0.f; int li = 0;
    for (int i = tid; i < VV; i += 256) {
        float v = row[i];
        if (v > m) { s *= expf(m - v); m = v; li = i; }
        s += expf(v - m);
    }
    smx[tid] = m; ssm[tid] = s; sid[tid] = li; __syncthreads();
    for (int st = 128; st > 0; st >>= 1) {
        if (tid < st) {
            float m2 = smx[tid + st], s2 = ssm[tid + st]; int i2 = sid[tid + st];
            float m1 = smx[tid];
            if (m2 > m1 || (m2 == m1 && i2 < sid[tid])) {
                ssm[tid] = ssm[tid] * expf(m1 - m2) + s2;
                smx[tid] = m2; sid[tid] = i2;
            } else {
                ssm[tid] += s2 * expf(m2 - smx[tid]);
            }
        }
        __syncthreads();
    }
    if (tid == 0) {
        float logZ = smx[0] + logf(ssm[0]);
        int pred = sid[0];
        int j = t & 15, ai = t >> 4, b = t >> 11;
        int anc = g_anchor[ai];
        int label = anc + j;
        int vl = label < SS;
        int safe = label < (SS - 1) ? label : (SS - 1);
        int tgt = input_ids[(size_t)b * SS + safe];
        float lmg = loss_mask[(size_t)b * SS + safe];
        float w = (g_keep[ai] && vl && j > 0) ? lmg : 0.f;
        float lp = row[tgt] - logZ;
        g_tokl[t] = w * (-lp);
        g_tokw[t] = w;
        g_toka[t] = (pred == tgt && w > 0.5f) ? 1.f : 0.f;
    }
}

__global__ void k_final(float* __restrict__ out) {
    __shared__ float s1[256], s2[256], s3[256];
    int tid = threadIdx.x;
    float a = 0.f, b = 0.f, c = 0.f;
    for (int t = tid; t < TT; t += 256) { a += g_tokl[t]; b += g_tokw[t]; c += g_toka[t]; }
    s1[tid] = a; s2[tid] = b; s3[tid] = c; __syncthreads();
    for (int s = 128; s > 0; s >>= 1) {
        if (tid < s) { s1[tid] += s1[tid + s]; s2[tid] += s2[tid + s]; s3[tid] += s3[tid + s]; }
        __syncthreads();
    }
    if (tid == 0) {
        float denom = s2[0] + 1e-6f;
        out[0] = s1[0] / denom;
        out[1] = s3[0] / denom;
    }
}

// ---------------- driver ----------------
extern "C" void kernel_launch(void* const* d_in, const int* in_sizes, int n_in,
                              void* d_out, int out_size) {
    const int*   input_ids     = (const int*)  d_in[0];
    const float* hidden_states = (const float*)d_in[1];
    const float* loss_mask     = (const float*)d_in[2];
    const float* rand_vals     = (const float*)d_in[3];
    const float* embed_table   = (const float*)d_in[4];
    const float* lm_head_w     = (const float*)d_in[5];
    const float* wq            = (const float*)d_in[6];
    const float* wk            = (const float*)d_in[7];
    const float* wv            = (const float*)d_in[8];
    const float* wo            = (const float*)d_in[9];
    const float* w_gate        = (const float*)d_in[10];
    const float* w_up          = (const float*)d_in[11];
    const float* w_down        = (const float*)d_in[12];
    const float* norm_attn     = (const float*)d_in[13];
    const float* norm_mlp      = (const float*)d_in[14];
    const float* norm_out      = (const float*)d_in[15];
    const float* norm_chs      = (const float*)d_in[16];
    float* out = (float*)d_out;

    static int smem_set = 0;
    if (!smem_set) {
        cudaFuncSetAttribute(k_tgemm, cudaFuncAttributeMaxDynamicSharedMemorySize, GSMEM);
        smem_set = 1;
    }

    float *px, *ppq, *ppk, *ppv, *po, *pff1, *pff2, *plog;
    __nv_bfloat16 *pkvin, *pattno, *ph, *pff1p;
    __nv_bfloat16 *pwqT, *pwkT, *pwvT, *pwoT, *pwgT, *pwuT, *pwdT, *plmb;
    cudaGetSymbolAddress((void**)&px,    g_x);
    cudaGetSymbolAddress((void**)&ppq,   g_pq);
    cudaGetSymbolAddress((void**)&ppk,   g_pk);
    cudaGetSymbolAddress((void**)&ppv,   g_pv);
    cudaGetSymbolAddress((void**)&po,    g_o);
    cudaGetSymbolAddress((void**)&pff1,  g_ff1);
    cudaGetSymbolAddress((void**)&pff2,  g_ff2);
    cudaGetSymbolAddress((void**)&plog,  g_logits);
    cudaGetSymbolAddress((void**)&pkvin, g_kvin_bf);
    cudaGetSymbolAddress((void**)&pattno,g_attno_bf);
    cudaGetSymbolAddress((void**)&ph,    g_h_bf);
    cudaGetSymbolAddress((void**)&pff1p, g_ff1p_bf);
    cudaGetSymbolAddress((void**)&pwqT,  g_wqT);
    cudaGetSymbolAddress((void**)&pwkT,  g_wkT);
    cudaGetSymbolAddress((void**)&pwvT,  g_wvT);
    cudaGetSymbolAddress((void**)&pwoT,  g_woT);
    cudaGetSymbolAddress((void**)&pwgT,  g_wgT);
    cudaGetSymbolAddress((void**)&pwuT,  g_wuT);
    cudaGetSymbolAddress((void**)&pwdT,  g_wdT);
    cudaGetSymbolAddress((void**)&plmb,  g_lmb);

    dim3 t32(32, 8);
    k_convT<<<dim3(DD / 32, DD / 32), t32>>>(wq, pwqT, DD, DD);
    k_convT<<<dim3(DD / 32, DD / 32), t32>>>(wk, pwkT, DD, DD);
    k_convT<<<dim3(DD / 32, DD / 32), t32>>>(wv, pwvT, DD, DD);
    k_convT<<<dim3(DD / 32, DD / 32), t32>>>(wo, pwoT, DD, DD);
    k_convT<<<dim3(DFF / 32, DD / 32), t32>>>(w_gate, pwgT, DD, DFF);
    k_convT<<<dim3(DFF / 32, DD / 32), t32>>>(w_up, pwuT, DD, DFF);
    k_convT<<<dim3(DD / 32, DFF / 32), t32>>>(w_down, pwdT, DFF, DD);
    k_conv<<<8192, 256>>>(lm_head_w, plmb, (size_t)VV * DD);

    k_rank<<<dim3(16, BB), 256>>>(rand_vals, loss_mask);
    k_compact<<<BB, 256>>>(input_ids);
    k_embed<<<TT, 256>>>(embed_table);
    k_rms_hq<<<TT, 256>>>(norm_attn);
    k_rms_hc<<<NAI, 256>>>(hidden_states, norm_chs);
    // QKV (grid.x = M tiles for L2-friendly ordering)
    k_tgemm<<<dim3(KVT / 128, DD / 128), 256, GSMEM>>>(pkvin, pwqT, ppq, KVT, DD, DD);
    k_tgemm<<<dim3(KVT / 128, DD / 128), 256, GSMEM>>>(pkvin, pwkT, ppk, KVT, DD, DD);
    k_tgemm<<<dim3(KVT / 128, DD / 128), 256, GSMEM>>>(pkvin, pwvT, ppv, KVT, DD, DD);
    k_rope<<<KVT, 256>>>();
    k_attn<<<TT, 288>>>();
    k_tgemm<<<dim3(TT / 128, DD / 128), 256, GSMEM>>>(pattno, pwoT, po, TT, DD, DD);
    k_resid<<<TT, 256>>>(px, po, 1);
    k_rms_tok_bf<<<TT, 256>>>(px, ph, norm_mlp);
    k_tgemm<<<dim3(TT / 128, DFF / 128), 256, GSMEM>>>(ph, pwgT, pff1, TT, DFF, DD);
    k_tgemm<<<dim3(TT / 128, DFF / 128), 256, GSMEM>>>(ph, pwuT, pff2, TT, DFF, DD);
    k_swiglu<<<8192, 256>>>(pff1, pff2, pff1p, (size_t)TT * DFF);
    k_tgemm<<<dim3(TT / 128, DD / 128), 256, GSMEM>>>(pff1p, pwdT, po, TT, DD, DFF);
    k_resid<<<TT, 256>>>(px, po, 0);
    k_rms_tok_bf<<<TT, 256>>>(px, ph, norm_out);
    k_tgemm<<<dim3(TT / 128, VV / 128), 256, GSMEM>>>(ph, plmb, plog, TT, VV, DD);
    k_loss<<<TT, 256>>>(input_ids, loss_mask);
    k_final<<<1, 256>>>(out);
}

// round 4
// speedup vs baseline: 6.5238x; 1.3076x over previous
#include <cuda_runtime.h>
#include <cuda_bf16.h>
#include <math.h>
#include <stdint.h>

// ---------------- problem constants ----------------
#define BB 2
#define SS 4096
#define DD 2048
#define VV 32000
#define HH 16
#define HD 128
#define BSQ 16
#define NA 128
#define MASK_ID 31999
#define DFF 8192
#define NRV (SS - BSQ + 1)          // 4081
#define TT (BB * NA * BSQ)          // 4096 tokens
#define KVT (BB * NA * (BSQ + 1))   // 4352 kv rows
#define NAI (BB * NA)               // 256 anchor slots
#define CQ  640                     // compact QKV rows (513 used, padded to 5*128)

// ---------------- scratch ----------------
__device__ int   g_anchor[NAI];
__device__ int   g_keep[NAI];
__device__ int   g_first[NAI];
__device__ int   g_ctxpos[NAI];
__device__ unsigned char g_sel[BB * 4096];

__device__ float g_x[(size_t)TT * DD];
__device__ float g_qkvc[(size_t)CQ * 3 * DD];   // compact qkv output [640 x 6144]
__device__ float g_pq[(size_t)KVT * DD];
__device__ float g_pk[(size_t)KVT * DD];
__device__ float g_pv[(size_t)KVT * DD];
__device__ float g_o[(size_t)TT * DD];
__device__ float g_ffc[(size_t)TT * 2 * DFF];   // gate|up concat [4096 x 16384]
__device__ float g_logits[(size_t)TT * VV];
__device__ float g_tokl[TT];
__device__ float g_tokw[TT];
__device__ float g_toka[TT];

__device__ __nv_bfloat16 g_kvin_bf[(size_t)CQ * DD];     // compact qkv input
__device__ __nv_bfloat16 g_attno_bf[(size_t)TT * DD];
__device__ __nv_bfloat16 g_h_bf[(size_t)TT * DD];
__device__ __nv_bfloat16 g_ff1p_bf[(size_t)TT * DFF];
__device__ __nv_bfloat16 g_wqkvT[(size_t)3 * DD * DD];   // [6144, 2048]
__device__ __nv_bfloat16 g_woT[(size_t)DD * DD];
__device__ __nv_bfloat16 g_wguT[(size_t)2 * DFF * DD];   // [16384, 2048]
__device__ __nv_bfloat16 g_wdT[(size_t)DD * DFF];
__device__ __nv_bfloat16 g_lmb[(size_t)VV * DD];

// ---------------- helpers ----------------
__device__ __forceinline__ uint32_t smem_u32(const void* p) {
    uint32_t a;
    asm("{ .reg .u64 t; cvta.to.shared.u64 t, %1; cvt.u32.u64 %0, t; }" : "=r"(a) : "l"(p));
    return a;
}
__device__ __forceinline__ void cpa16(uint32_t dst, const void* src) {
    asm volatile("cp.async.cg.shared.global [%0], [%1], 16;" :: "r"(dst), "l"(src));
}
#define CP_COMMIT() asm volatile("cp.async.commit_group;" ::: "memory")
#define CP_WAIT1()  asm volatile("cp.async.wait_group 1;" ::: "memory")

__device__ __forceinline__ void ldsm4(uint32_t& r0, uint32_t& r1, uint32_t& r2, uint32_t& r3,
                                      uint32_t addr) {
    asm volatile("ldmatrix.sync.aligned.m8n8.x4.shared.b16 {%0,%1,%2,%3}, [%4];"
                 : "=r"(r0), "=r"(r1), "=r"(r2), "=r"(r3) : "r"(addr));
}
__device__ __forceinline__ void mma16816(float* c, const uint32_t* a, const uint32_t* b) {
    asm volatile("mma.sync.aligned.m16n8k16.row.col.f32.bf16.bf16.f32 "
                 "{%0,%1,%2,%3}, {%4,%5,%6,%7}, {%8,%9}, {%0,%1,%2,%3};"
                 : "+f"(c[0]), "+f"(c[1]), "+f"(c[2]), "+f"(c[3])
                 : "r"(a[0]), "r"(a[1]), "r"(a[2]), "r"(a[3]), "r"(b[0]), "r"(b[1]));
}

// ---------------- anchor selection ----------------
__global__ void k_rank(const float* __restrict__ rand_vals,
                       const float* __restrict__ loss_mask) {
    int b = blockIdx.y;
    __shared__ float srv[NRV];
    const float* rv = rand_vals + (size_t)b * NRV;
    const float* lm = loss_mask + (size_t)b * SS;
    for (int i = threadIdx.x; i < NRV; i += blockDim.x)
        srv[i] = (lm[i] > 0.5f) ? rv[i] : 2.0f;
    __syncthreads();
    int i = blockIdx.x * 256 + threadIdx.x;
    if (i < NRV) {
        float vi = srv[i];
        int r = 0;
        for (int j = 0; j < NRV; j++) {
            float vj = srv[j];
            r += (vj < vi) || (vj == vi && j < i);
        }
        g_sel[b * 4096 + i] = (r < NA && vi < 1.5f) ? 1 : 0;
    }
}

__global__ void k_compact(const int* __restrict__ input_ids) {
    int b = blockIdx.x;
    __shared__ unsigned char s[NRV];
    for (int i = threadIdx.x; i < NRV; i += blockDim.x) s[i] = g_sel[b * 4096 + i];
    __syncthreads();
    if (threadIdx.x == 0) {
        int slot = 0;
        int tmp[NA];
        for (int i = 0; i < NRV && slot < NA; i++)
            if (s[i]) tmp[slot++] = i;
        for (int k = 0; k < NA; k++) {
            int kp = (k < slot) ? 1 : 0;
            int a  = kp ? tmp[k] : 0;
            int ai = b * NA + k;
            g_anchor[ai] = a;
            g_keep[ai]   = kp;
            int clipped = a < (SS - 1) ? a : (SS - 1);
            g_first[ai]  = kp ? input_ids[(size_t)b * SS + clipped] : MASK_ID;
            g_ctxpos[ai] = (a - 1 > 0) ? (a - 1) : 0;
        }
    }
}

// ---------------- embedding ----------------
__global__ void k_embed(const float* __restrict__ emb) {
    int t  = blockIdx.x;
    int j  = t & 15;
    int ai = t >> 4;
    int id = (j == 0) ? g_first[ai] : MASK_ID;
    const float4* src = (const float4*)(emb + (size_t)id * DD);
    float4* dst = (float4*)(g_x + (size_t)t * DD);
    for (int i = threadIdx.x; i < DD / 4; i += blockDim.x) dst[i] = src[i];
}

// ---------------- rmsnorm -> bf16 ----------------
__device__ __forceinline__ float blk_sum(float v, float* sh) {
    int tid = threadIdx.x;
    sh[tid] = v; __syncthreads();
    for (int s = blockDim.x / 2; s > 0; s >>= 1) {
        if (tid < s) sh[tid] += sh[tid + s];
        __syncthreads();
    }
    return sh[0];
}
__device__ __forceinline__ void rms_row_bf(const float* __restrict__ in,
                                           __nv_bfloat16* __restrict__ out,
                                           const float* __restrict__ w, float* sh) {
    float ss = 0.f;
    for (int c = threadIdx.x; c < DD; c += blockDim.x) { float v = in[c]; ss += v * v; }
    ss = blk_sum(ss, sh);
    float scale = rsqrtf(ss / (float)DD + 1e-6f);
    for (int c = threadIdx.x; c < DD; c += blockDim.x)
        out[c] = __float2bfloat16(in[c] * scale * w[c]);
}
// compact QKV input: rows 0..255 ctx, 256..511 first-token hq, 512 mask hq
__global__ void k_rms_hc(const float* __restrict__ hs, const float* __restrict__ w) {
    __shared__ float sh[256];
    int r = blockIdx.x;
    int b = r / NA;
    rms_row_bf(hs + ((size_t)b * SS + g_ctxpos[r]) * DD, g_kvin_bf + (size_t)r * DD, w, sh);
}
__global__ void k_rms_hq(const float* __restrict__ emb, const float* __restrict__ w) {
    __shared__ float sh[256];
    int r = blockIdx.x;               // 0..256
    const float* in = (r < NAI) ? (g_x + (size_t)(r * 16) * DD)
                                : (emb + (size_t)MASK_ID * DD);
    rms_row_bf(in, g_kvin_bf + (size_t)(NAI + r) * DD, w, sh);
}
__global__ void k_rms_tok_bf(const float* __restrict__ in, __nv_bfloat16* __restrict__ out,
                             const float* __restrict__ w) {
    __shared__ float sh[256];
    int t = blockIdx.x;
    rms_row_bf(in + (size_t)t * DD, out + (size_t)t * DD, w, sh);
}

// ---------------- weight prep ----------------
__global__ void k_convT(const float* __restrict__ W, __nv_bfloat16* __restrict__ Wt,
                        int K, int N) {
    __shared__ float t[32][33];
    int n0 = blockIdx.x * 32, k0 = blockIdx.y * 32;
    int tx = threadIdx.x, ty = threadIdx.y;
#pragma unroll
    for (int j = 0; j < 32; j += 8)
        t[ty + j][tx] = W[(size_t)(k0 + ty + j) * N + n0 + tx];
    __syncthreads();
#pragma unroll
    for (int j = 0; j < 32; j += 8)
        Wt[(size_t)(n0 + ty + j) * K + k0 + tx] = __float2bfloat16(t[tx][ty + j]);
}
__global__ void k_conv(const float* __restrict__ in, __nv_bfloat16* __restrict__ out, size_t n) {
    for (size_t i = (size_t)blockIdx.x * blockDim.x + threadIdx.x; i < n;
         i += (size_t)gridDim.x * blockDim.x)
        out[i] = __float2bfloat16(in[i]);
}

// ---------------- bf16 mma.sync GEMM: C[M,N] = A[M,K] @ Bt[N,K]^T ----------------
// block 128x128x32, 256 thr (8 warps 4x2), warp 32x64, 3-stage cp.async, 2 CTAs/SM
#define GSTG 3
#define ROWB 80
#define OPB  (128 * ROWB)
#define STGB (2 * OPB)
#define GSMEM (GSTG * STGB)           // 61440

__device__ __forceinline__ void g_load_stage(uint32_t st, const __nv_bfloat16* Ab,
                                             const __nv_bfloat16* Bb, int K, int kb, int tid) {
#pragma unroll
    for (int i = 0; i < 2; i++) {
        int id = tid + i * 256;
        int r = id >> 2, ch = id & 3;
        cpa16(st + r * ROWB + ch * 16,       Ab + (size_t)r * K + kb * 32 + ch * 8);
        cpa16(st + OPB + r * ROWB + ch * 16, Bb + (size_t)r * K + kb * 32 + ch * 8);
    }
}

__global__ void __launch_bounds__(256, 2)
k_tgemm(const __nv_bfloat16* __restrict__ A, const __nv_bfloat16* __restrict__ Bt,
        float* __restrict__ C, int M, int N, int K) {
    extern __shared__ char smem[];
    uint32_t sb = smem_u32(smem);
    int tid = threadIdx.x;
    int lane = tid & 31, w = tid >> 5;
    int wm = w >> 1, wn = w & 1;
    int m0 = blockIdx.x * 128, n0 = blockIdx.y * 128;
    const __nv_bfloat16* Ab = A + (size_t)m0 * K;
    const __nv_bfloat16* Bb = Bt + (size_t)n0 * K;

    float acc[2][8][4];
#pragma unroll
    for (int i = 0; i < 2; i++)
#pragma unroll
        for (int j = 0; j < 8; j++)
#pragma unroll
            for (int q = 0; q < 4; q++) acc[i][j][q] = 0.f;

    int nk = K >> 5;
#pragma unroll
    for (int s = 0; s < GSTG - 1; s++) {
        g_load_stage(sb + s * STGB, Ab, Bb, K, s, tid);
        CP_COMMIT();
    }

    uint32_t aoff = (uint32_t)((wm * 32 + (lane & 15)) * ROWB + (lane >> 4) * 16);
    uint32_t boff = (uint32_t)(OPB + (wn * 64 + (lane & 7) + ((lane >> 4) & 1) * 8) * ROWB +
                               ((lane >> 3) & 1) * 16);

    for (int kb = 0; kb < nk; kb++) {
        uint32_t st = sb + (kb % GSTG) * STGB;
        CP_WAIT1();
        __syncthreads();
        // issue next-stage loads early (writes stage (kb-1)%3 — safe after the barrier)
        if (kb + GSTG - 1 < nk)
            g_load_stage(sb + ((kb + GSTG - 1) % GSTG) * STGB, Ab, Bb, K, kb + GSTG - 1, tid);
        CP_COMMIT();

#pragma unroll
        for (int ks = 0; ks < 2; ks++) {
            uint32_t a[2][4], b[4][4];
#pragma unroll
            for (int mt = 0; mt < 2; mt++)
                ldsm4(a[mt][0], a[mt][1], a[mt][2], a[mt][3],
                      st + aoff + mt * 16 * ROWB + ks * 32);
#pragma unroll
            for (int p = 0; p < 4; p++)
                ldsm4(b[p][0], b[p][1], b[p][2], b[p][3],
                      st + boff + p * 16 * ROWB + ks * 32);
#pragma unroll
            for (int mt = 0; mt < 2; mt++)
#pragma unroll
                for (int p = 0; p < 4; p++) {
                    mma16816(acc[mt][2 * p],     a[mt], &b[p][0]);
                    mma16816(acc[mt][2 * p + 1], a[mt], &b[p][2]);
                }
        }
    }

#pragma unroll
    for (int mt = 0; mt < 2; mt++) {
        int r0 = m0 + wm * 32 + mt * 16 + (lane >> 2);
#pragma unroll
        for (int nt = 0; nt < 8; nt++) {
            int c = n0 + wn * 64 + nt * 8 + (lane & 3) * 2;
            *(float2*)(C + (size_t)r0 * N + c)       = make_float2(acc[mt][nt][0], acc[mt][nt][1]);
            *(float2*)(C + (size_t)(r0 + 8) * N + c) = make_float2(acc[mt][nt][2], acc[mt][nt][3]);
        }
    }
}

// ---------------- rope + gather compact -> full q/k/v ----------------
__global__ void k_ropegather() {
    int r  = blockIdx.x;               // 0..4351
    int kk = r % 17;
    int ai = r / 17;
    int crow = (kk == 0) ? ai : ((kk == 1) ? (NAI + ai) : 512);
    int pos = (kk == 0) ? g_ctxpos[ai] : (g_anchor[ai] + kk - 1);
    const float* qs = g_qkvc + (size_t)crow * (3 * DD);
    const float* ks = qs + DD;
    const float* vs = qs + 2 * DD;
    float* qo = g_pq + (size_t)r * DD;
    float* ko = g_pk + (size_t)r * DD;
    float* vo = g_pv + (size_t)r * DD;
    for (int p = threadIdx.x; p < HH * 64; p += blockDim.x) {
        int h = p >> 6, d = p & 63;
        float inv = expf(-(float)d * 0.14391156965722198f);
        float ang = (float)pos * inv;
        float s, c;
        sincosf(ang, &s, &c);
        int c1 = h * HD + d, c2 = c1 + 64;
        float k1 = ks[c1], k2 = ks[c2];
        ko[c1] = k1 * c - k2 * s;
        ko[c2] = k2 * c + k1 * s;
        float q1 = qs[c1], q2 = qs[c2];
        qo[c1] = q1 * c - q2 * s;
        qo[c2] = q2 * c + q1 * s;
        vo[c1] = vs[c1];
        vo[c2] = vs[c2];
    }
}

// ---------------- attention ----------------
__global__ void __launch_bounds__(288) k_attn() {
    int g = blockIdx.x;
    int h  = g & 15;
    int na = (g >> 4) & 127;
    int b  = g >> 11;
    int base = (b * NA + na) * 17;
    __shared__ float sk[17][HD], sv[17][HD], sq[BSQ][HD], sw[BSQ][18];
    int tid = threadIdx.x;
    for (int i = tid; i < 17 * HD; i += 288) {
        int r = i >> 7, c = i & 127;
        size_t off = (size_t)(base + r) * DD + h * HD + c;
        sk[r][c] = g_pk[off];
        sv[r][c] = g_pv[off];
    }
    for (int i = tid; i < BSQ * HD; i += 288) {
        int r = i >> 7, c = i & 127;
        sq[r][c] = g_pq[(size_t)(base + 1 + r) * DD + h * HD + c];
    }
    __syncthreads();
    if (tid < BSQ * 17) {
        int j = tid / 17, kk = tid % 17;
        float d = 0.f;
#pragma unroll 8
        for (int c = 0; c < HD; c++) d += sq[j][c] * sk[kk][c];
        sw[j][kk] = d * 0.08838834764831845f;
    }
    __syncthreads();
    if (tid < BSQ) {
        float m = -3.4e38f;
        for (int kk = 0; kk < 17; kk++) m = fmaxf(m, sw[tid][kk]);
        float s = 0.f;
        for (int kk = 0; kk < 17; kk++) { float e = expf(sw[tid][kk] - m); sw[tid][kk] = e; s += e; }
        float invs = 1.f / s;
        for (int kk = 0; kk < 17; kk++) sw[tid][kk] *= invs;
    }
    __syncthreads();
    for (int i = tid; i < BSQ * HD; i += 288) {
        int j = i >> 7, c = i & 127;
        float o = 0.f;
#pragma unroll
        for (int kk = 0; kk < 17; kk++) o += sw[j][kk] * sv[kk][c];
        g_attno_bf[(size_t)(b * 2048 + na * BSQ + j) * DD + h * HD + c] = __float2bfloat16(o);
    }
}

// ---------------- residual / swiglu ----------------
__global__ void k_resid(float* __restrict__ x, const float* __restrict__ o, int useKeep) {
    int t = blockIdx.x;
    float m = 1.f;
    if (useKeep) m = (float)g_keep[t >> 4];
    size_t off = (size_t)t * DD;
    for (int c = threadIdx.x; c < DD; c += blockDim.x) x[off + c] += m * o[off + c];
}
__global__ void k_swiglu(const float* __restrict__ ffc, __nv_bfloat16* __restrict__ out) {
    size_t n = (size_t)TT * DFF;
    for (size_t i = (size_t)blockIdx.x * blockDim.x + threadIdx.x; i < n;
         i += (size_t)gridDim.x * blockDim.x) {
        size_t r = i >> 13, c = i & (DFF - 1);
        float x = ffc[r * (2 * DFF) + c];
        float u = ffc[r * (2 * DFF) + DFF + c];
        float s = x / (1.f + expf(-x));
        out[i] = __float2bfloat16(s * u);
    }
}

// ---------------- fused CE loss / argmax ----------------
__global__ void k_loss(const int* __restrict__ input_ids, const float* __restrict__ loss_mask) {
    int t = blockIdx.x;
    const float* row = g_logits + (size_t)t * VV;
    int tid = threadIdx.x;
    __shared__ float smx[256]; __shared__ float ssm[256]; __shared__ int sid[256];
    float m = -3.4e38f, s = 0.f; int li = 0;
    for (int i = tid; i < VV; i += 256) {
        float v = row[i];
        if (v > m) { s *= expf(m - v); m = v; li = i; }
        s += expf(v - m);
    }
    smx[tid] = m; ssm[tid] = s; sid[tid] = li; __syncthreads();
    for (int st = 128; st > 0; st >>= 1) {
        if (tid < st) {
            float m2 = smx[tid + st], s2 = ssm[tid + st]; int i2 = sid[tid + st];
            float m1 = smx[tid];
            if (m2 > m1 || (m2 == m1 && i2 < sid[tid])) {
                ssm[tid] = ssm[tid] * expf(m1 - m2) + s2;
                smx[tid] = m2; sid[tid] = i2;
            } else {
                ssm[tid] += s2 * expf(m2 - smx[tid]);
            }
        }
        __syncthreads();
    }
    if (tid == 0) {
        float logZ = smx[0] + logf(ssm[0]);
        int pred = sid[0];
        int j = t & 15, ai = t >> 4, b = t >> 11;
        int anc = g_anchor[ai];
        int label = anc + j;
        int vl = label < SS;
        int safe = label < (SS - 1) ? label : (SS - 1);
        int tgt = input_ids[(size_t)b * SS + safe];
        float lmg = loss_mask[(size_t)b * SS + safe];
        float w = (g_keep[ai] && vl && j > 0) ? lmg : 0.f;
        float lp = row[tgt] - logZ;
        g_tokl[t] = w * (-lp);
        g_tokw[t] = w;
        g_toka[t] = (pred == tgt && w > 0.5f) ? 1.f : 0.f;
    }
}

__global__ void k_final(float* __restrict__ out) {
    __shared__ float s1[256], s2[256], s3[256];
    int tid = threadIdx.x;
    float a = 0.f, b = 0.f, c = 0.f;
    for (int t = tid; t < TT; t += 256) { a += g_tokl[t]; b += g_tokw[t]; c += g_toka[t]; }
    s1[tid] = a; s2[tid] = b; s3[tid] = c; __syncthreads();
    for (int s = 128; s > 0; s >>= 1) {
        if (tid < s) { s1[tid] += s1[tid + s]; s2[tid] += s2[tid + s]; s3[tid] += s3[tid + s]; }
        __syncthreads();
    }
    if (tid == 0) {
        float denom = s2[0] + 1e-6f;
        out[0] = s1[0] / denom;
        out[1] = s3[0] / denom;
    }
}

// ---------------- driver ----------------
extern "C" void kernel_launch(void* const* d_in, const int* in_sizes, int n_in,
                              void* d_out, int out_size) {
    const int*   input_ids     = (const int*)  d_in[0];
    const float* hidden_states = (const float*)d_in[1];
    const float* loss_mask     = (const float*)d_in[2];
    const float* rand_vals     = (const float*)d_in[3];
    const float* embed_table   = (const float*)d_in[4];
    const float* lm_head_w     = (const float*)d_in[5];
    const float* wq            = (const float*)d_in[6];
    const float* wk            = (const float*)d_in[7];
    const float* wv            = (const float*)d_in[8];
    const float* wo            = (const float*)d_in[9];
    const float* w_gate        = (const float*)d_in[10];
    const float* w_up          = (const float*)d_in[11];
    const float* w_down        = (const float*)d_in[12];
    const float* norm_attn     = (const float*)d_in[13];
    const float* norm_mlp      = (const float*)d_in[14];
    const float* norm_out      = (const float*)d_in[15];
    const float* norm_chs      = (const float*)d_in[16];
    float* out = (float*)d_out;

    static int smem_set = 0;
    if (!smem_set) {
        cudaFuncSetAttribute(k_tgemm, cudaFuncAttributeMaxDynamicSharedMemorySize, GSMEM);
        smem_set = 1;
    }

    float *px, *pqkvc, *po, *pffc, *plog;
    __nv_bfloat16 *pkvin, *pattno, *ph, *pff1p;
    __nv_bfloat16 *pwqkvT, *pwoT, *pwguT, *pwdT, *plmb;
    cudaGetSymbolAddress((void**)&px,     g_x);
    cudaGetSymbolAddress((void**)&pqkvc,  g_qkvc);
    cudaGetSymbolAddress((void**)&po,     g_o);
    cudaGetSymbolAddress((void**)&pffc,   g_ffc);
    cudaGetSymbolAddress((void**)&plog,   g_logits);
    cudaGetSymbolAddress((void**)&pkvin,  g_kvin_bf);
    cudaGetSymbolAddress((void**)&pattno, g_attno_bf);
    cudaGetSymbolAddress((void**)&ph,     g_h_bf);
    cudaGetSymbolAddress((void**)&pff1p,  g_ff1p_bf);
    cudaGetSymbolAddress((void**)&pwqkvT, g_wqkvT);
    cudaGetSymbolAddress((void**)&pwoT,   g_woT);
    cudaGetSymbolAddress((void**)&pwguT,  g_wguT);
    cudaGetSymbolAddress((void**)&pwdT,   g_wdT);
    cudaGetSymbolAddress((void**)&plmb,   g_lmb);

    dim3 t32(32, 8);
    // weights: concat wq|wk|wv rows, wg|wu rows
    k_convT<<<dim3(DD / 32, DD / 32), t32>>>(wq, pwqkvT, DD, DD);
    k_convT<<<dim3(DD / 32, DD / 32), t32>>>(wk, pwqkvT + (size_t)DD * DD, DD, DD);
    k_convT<<<dim3(DD / 32, DD / 32), t32>>>(wv, pwqkvT + (size_t)2 * DD * DD, DD, DD);
    k_convT<<<dim3(DD / 32, DD / 32), t32>>>(wo, pwoT, DD, DD);
    k_convT<<<dim3(DFF / 32, DD / 32), t32>>>(w_gate, pwguT, DD, DFF);
    k_convT<<<dim3(DFF / 32, DD / 32), t32>>>(w_up, pwguT + (size_t)DFF * DD, DD, DFF);
    k_convT<<<dim3(DD / 32, DFF / 32), t32>>>(w_down, pwdT, DFF, DD);
    k_conv<<<8192, 256>>>(lm_head_w, plmb, (size_t)VV * DD);

    k_rank<<<dim3(16, BB), 256>>>(rand_vals, loss_mask);
    k_compact<<<BB, 256>>>(input_ids);
    k_embed<<<TT, 256>>>(embed_table);
    // compact QKV inputs: 256 ctx + 256 first-tok + 1 mask row
    k_rms_hc<<<NAI, 256>>>(hidden_states, norm_chs);
    k_rms_hq<<<NAI + 1, 256>>>(embed_table, norm_attn);
    // fused compact QKV projection: [640 x 2048] @ [6144 x 2048]^T
    k_tgemm<<<dim3(CQ / 128, 3 * DD / 128), 256, GSMEM>>>(pkvin, pwqkvT, pqkvc, CQ, 3 * DD, DD);
    k_ropegather<<<KVT, 256>>>();
    k_attn<<<TT, 288>>>();
    k_tgemm<<<dim3(TT / 128, DD / 128), 256, GSMEM>>>(pattno, pwoT, po, TT, DD, DD);
    k_resid<<<TT, 256>>>(px, po, 1);
    k_rms_tok_bf<<<TT, 256>>>(px, ph, norm_mlp);
    // fused gate|up: [4096 x 2048] @ [16384 x 2048]^T
    k_tgemm<<<dim3(TT / 128, 2 * DFF / 128), 256, GSMEM>>>(ph, pwguT, pffc, TT, 2 * DFF, DD);
    k_swiglu<<<8192, 256>>>(pffc, pff1p);
    k_tgemm<<<dim3(TT / 128, DD / 128), 256, GSMEM>>>(pff1p, pwdT, po, TT, DD, DFF);
    k_resid<<<TT, 256>>>(px, po, 0);
    k_rms_tok_bf<<<TT, 256>>>(px, ph, norm_out);
    k_tgemm<<<dim3(TT / 128, VV / 128), 256, GSMEM>>>(ph, plmb, plog, TT, VV, DD);
    k_loss<<<TT, 256>>>(input_ids, loss_mask);
    k_final<<<1, 256>>>(out);
}

// round 5
// speedup vs baseline: 6.8643x; 1.0522x over previous
#include <cuda_runtime.h>
#include <cuda_bf16.h>
#include <math.h>
#include <stdint.h>

// ---------------- problem constants ----------------
#define BB 2
#define SS 4096
#define DD 2048
#define VV 32000
#define HH 16
#define HD 128
#define BSQ 16
#define NA 128
#define MASK_ID 31999
#define DFF 8192
#define NRV (SS - BSQ + 1)          // 4081
#define TT (BB * NA * BSQ)          // 4096 tokens
#define KVT (BB * NA * (BSQ + 1))   // 4352 kv rows
#define NAI (BB * NA)               // 256 anchor slots
#define CQ  640                     // compact QKV rows (513 used)
#define NCH (VV / 64)               // 500 softmax chunks per row

// ---------------- scratch ----------------
__device__ int   g_anchor[NAI];
__device__ int   g_keep[NAI];
__device__ int   g_first[NAI];
__device__ int   g_ctxpos[NAI];
__device__ unsigned char g_sel[BB * 4096];

__device__ float g_x[(size_t)TT * DD];
__device__ float g_qkvc[(size_t)CQ * 3 * DD];
__device__ float g_pq[(size_t)KVT * DD];
__device__ float g_pk[(size_t)KVT * DD];
__device__ float g_pv[(size_t)KVT * DD];
__device__ float g_o[(size_t)TT * DD];
__device__ float g_tokl[TT];
__device__ float g_tokw[TT];
__device__ float g_toka[TT];
// fused-CE partials
__device__ float g_pmax[(size_t)TT * NCH];
__device__ float g_psum[(size_t)TT * NCH];
__device__ int   g_pidx[(size_t)TT * NCH];
__device__ float g_tgtlog[TT];
__device__ int   g_tgt[TT];
__device__ float g_wgt[TT];

__device__ __nv_bfloat16 g_kvin_bf[(size_t)CQ * DD];
__device__ __nv_bfloat16 g_attno_bf[(size_t)TT * DD];
__device__ __nv_bfloat16 g_h_bf[(size_t)TT * DD];
__device__ __nv_bfloat16 g_ffc_bf[(size_t)TT * 2 * DFF];   // gate|up bf16
__device__ __nv_bfloat16 g_ff1p_bf[(size_t)TT * DFF];
__device__ __nv_bfloat16 g_wqkvT[(size_t)3 * DD * DD];
__device__ __nv_bfloat16 g_woT[(size_t)DD * DD];
__device__ __nv_bfloat16 g_wguT[(size_t)2 * DFF * DD];
__device__ __nv_bfloat16 g_wdT[(size_t)DD * DFF];
__device__ __nv_bfloat16 g_lmb[(size_t)VV * DD];

// ---------------- helpers ----------------
__device__ __forceinline__ uint32_t smem_u32(const void* p) {
    uint32_t a;
    asm("{ .reg .u64 t; cvta.to.shared.u64 t, %1; cvt.u32.u64 %0, t; }" : "=r"(a) : "l"(p));
    return a;
}
__device__ __forceinline__ void cpa16(uint32_t dst, const void* src) {
    asm volatile("cp.async.cg.shared.global [%0], [%1], 16;" :: "r"(dst), "l"(src));
}
#define CP_COMMIT() asm volatile("cp.async.commit_group;" ::: "memory")
#define CP_WAIT1()  asm volatile("cp.async.wait_group 1;" ::: "memory")

__device__ __forceinline__ void ldsm4(uint32_t& r0, uint32_t& r1, uint32_t& r2, uint32_t& r3,
                                      uint32_t addr) {
    asm volatile("ldmatrix.sync.aligned.m8n8.x4.shared.b16 {%0,%1,%2,%3}, [%4];"
                 : "=r"(r0), "=r"(r1), "=r"(r2), "=r"(r3) : "r"(addr));
}
__device__ __forceinline__ void mma16816(float* c, const uint32_t* a, const uint32_t* b) {
    asm volatile("mma.sync.aligned.m16n8k16.row.col.f32.bf16.bf16.f32 "
                 "{%0,%1,%2,%3}, {%4,%5,%6,%7}, {%8,%9}, {%0,%1,%2,%3};"
                 : "+f"(c[0]), "+f"(c[1]), "+f"(c[2]), "+f"(c[3])
                 : "r"(a[0]), "r"(a[1]), "r"(a[2]), "r"(a[3]), "r"(b[0]), "r"(b[1]));
}

// ---------------- anchor selection ----------------
__global__ void k_rank(const float* __restrict__ rand_vals,
                       const float* __restrict__ loss_mask) {
    int b = blockIdx.y;
    __shared__ float srv[NRV];
    const float* rv = rand_vals + (size_t)b * NRV;
    const float* lm = loss_mask + (size_t)b * SS;
    for (int i = threadIdx.x; i < NRV; i += blockDim.x)
        srv[i] = (lm[i] > 0.5f) ? rv[i] : 2.0f;
    __syncthreads();
    int i = blockIdx.x * 256 + threadIdx.x;
    if (i < NRV) {
        float vi = srv[i];
        int r = 0;
        for (int j = 0; j < NRV; j++) {
            float vj = srv[j];
            r += (vj < vi) || (vj == vi && j < i);
        }
        g_sel[b * 4096 + i] = (r < NA && vi < 1.5f) ? 1 : 0;
    }
}

__global__ void k_compact(const int* __restrict__ input_ids) {
    int b = blockIdx.x;
    __shared__ unsigned char s[NRV];
    for (int i = threadIdx.x; i < NRV; i += blockDim.x) s[i] = g_sel[b * 4096 + i];
    __syncthreads();
    if (threadIdx.x == 0) {
        int slot = 0;
        int tmp[NA];
        for (int i = 0; i < NRV && slot < NA; i++)
            if (s[i]) tmp[slot++] = i;
        for (int k = 0; k < NA; k++) {
            int kp = (k < slot) ? 1 : 0;
            int a  = kp ? tmp[k] : 0;
            int ai = b * NA + k;
            g_anchor[ai] = a;
            g_keep[ai]   = kp;
            int clipped = a < (SS - 1) ? a : (SS - 1);
            g_first[ai]  = kp ? input_ids[(size_t)b * SS + clipped] : MASK_ID;
            g_ctxpos[ai] = (a - 1 > 0) ? (a - 1) : 0;
        }
    }
}

// targets & weights per token (consumed by fused-CE epilogue + k_loss2)
__global__ void k_prep(const int* __restrict__ input_ids, const float* __restrict__ loss_mask) {
    int t = blockIdx.x * 256 + threadIdx.x;
    if (t >= TT) return;
    int j = t & 15, ai = t >> 4, b = t >> 11;
    int anc = g_anchor[ai];
    int label = anc + j;
    int vl = label < SS;
    int safe = label < (SS - 1) ? label : (SS - 1);
    g_tgt[t] = input_ids[(size_t)b * SS + safe];
    float lmg = loss_mask[(size_t)b * SS + safe];
    g_wgt[t] = (g_keep[ai] && vl && j > 0) ? lmg : 0.f;
}

// ---------------- embedding ----------------
__global__ void k_embed(const float* __restrict__ emb) {
    int t  = blockIdx.x;
    int j  = t & 15;
    int ai = t >> 4;
    int id = (j == 0) ? g_first[ai] : MASK_ID;
    const float4* src = (const float4*)(emb + (size_t)id * DD);
    float4* dst = (float4*)(g_x + (size_t)t * DD);
    for (int i = threadIdx.x; i < DD / 4; i += blockDim.x) dst[i] = src[i];
}

// ---------------- rmsnorm -> bf16 ----------------
__device__ __forceinline__ float blk_sum(float v, float* sh) {
    int tid = threadIdx.x;
    sh[tid] = v; __syncthreads();
    for (int s = blockDim.x / 2; s > 0; s >>= 1) {
        if (tid < s) sh[tid] += sh[tid + s];
        __syncthreads();
    }
    return sh[0];
}
__device__ __forceinline__ void rms_row_bf(const float* __restrict__ in,
                                           __nv_bfloat16* __restrict__ out,
                                           const float* __restrict__ w, float* sh) {
    float ss = 0.f;
    for (int c = threadIdx.x; c < DD; c += blockDim.x) { float v = in[c]; ss += v * v; }
    ss = blk_sum(ss, sh);
    float scale = rsqrtf(ss / (float)DD + 1e-6f);
    for (int c = threadIdx.x; c < DD; c += blockDim.x)
        out[c] = __float2bfloat16(in[c] * scale * w[c]);
}
__global__ void k_rms_hc(const float* __restrict__ hs, const float* __restrict__ w) {
    __shared__ float sh[256];
    int r = blockIdx.x;
    int b = r / NA;
    rms_row_bf(hs + ((size_t)b * SS + g_ctxpos[r]) * DD, g_kvin_bf + (size_t)r * DD, w, sh);
}
__global__ void k_rms_hq(const float* __restrict__ emb, const float* __restrict__ w) {
    __shared__ float sh[256];
    int r = blockIdx.x;
    const float* in = (r < NAI) ? (g_x + (size_t)(r * 16) * DD)
                                : (emb + (size_t)MASK_ID * DD);
    rms_row_bf(in, g_kvin_bf + (size_t)(NAI + r) * DD, w, sh);
}
__global__ void k_rms_tok_bf(const float* __restrict__ in, __nv_bfloat16* __restrict__ out,
                             const float* __restrict__ w) {
    __shared__ float sh[256];
    int t = blockIdx.x;
    rms_row_bf(in + (size_t)t * DD, out + (size_t)t * DD, w, sh);
}

// ---------------- weight prep ----------------
// W: K x N fp32 row-major -> Wt: N x K bf16 row-major; 64x64 tiles, vectorized
__global__ void __launch_bounds__(256) k_convT(const float* __restrict__ W,
                                               __nv_bfloat16* __restrict__ Wt, int K, int N) {
    __shared__ float s[64][65];
    int n0 = blockIdx.x * 64, k0 = blockIdx.y * 64;
    int tid = threadIdx.x;
#pragma unroll
    for (int i = 0; i < 4; i++) {
        int id = tid + i * 256;       // 0..1023
        int r = id >> 4;              // k row 0..63
        int c4 = id & 15;             // float4 col
        float4 v = *(const float4*)(W + (size_t)(k0 + r) * N + n0 + c4 * 4);
        s[c4 * 4 + 0][r] = v.x;
        s[c4 * 4 + 1][r] = v.y;
        s[c4 * 4 + 2][r] = v.z;
        s[c4 * 4 + 3][r] = v.w;
    }
    __syncthreads();
#pragma unroll
    for (int i = 0; i < 2; i++) {
        int id = tid + i * 256;       // 0..511
        int r = id >> 3;              // n row 0..63
        int c8 = id & 7;
        __align__(16) __nv_bfloat16 tmp[8];
#pragma unroll
        for (int j = 0; j < 8; j++) tmp[j] = __float2bfloat16(s[r][c8 * 8 + j]);
        *(uint4*)(Wt + (size_t)(n0 + r) * K + k0 + c8 * 8) = *(uint4*)tmp;
    }
}
// vectorized straight convert (8 elems/thread)
__global__ void k_conv(const float* __restrict__ in, __nv_bfloat16* __restrict__ out, size_t n8) {
    for (size_t i = (size_t)blockIdx.x * blockDim.x + threadIdx.x; i < n8;
         i += (size_t)gridDim.x * blockDim.x) {
        size_t base = i * 8;
        float4 a = *(const float4*)(in + base);
        float4 b = *(const float4*)(in + base + 4);
        __align__(16) __nv_bfloat16 tmp[8];
        tmp[0] = __float2bfloat16(a.x); tmp[1] = __float2bfloat16(a.y);
        tmp[2] = __float2bfloat16(a.z); tmp[3] = __float2bfloat16(a.w);
        tmp[4] = __float2bfloat16(b.x); tmp[5] = __float2bfloat16(b.y);
        tmp[6] = __float2bfloat16(b.z); tmp[7] = __float2bfloat16(b.w);
        *(uint4*)(out + base) = *(uint4*)tmp;
    }
}

// ---------------- bf16 mma.sync GEMM ----------------
// block 128x128x32, 256 thr, warp 32x64, 3-stage cp.async
// EPI: 0 = fp32 C, 1 = bf16 C, 2 = fused softmax-CE partials (lm_head)
#define GSTG 3
#define ROWB 80
#define OPB  (128 * ROWB)
#define STGB (2 * OPB)
#define GSMEM (GSTG * STGB)

__device__ __forceinline__ void g_load_stage(uint32_t st, const __nv_bfloat16* Ab,
                                             const __nv_bfloat16* Bb, int K, int kb, int tid) {
#pragma unroll
    for (int i = 0; i < 2; i++) {
        int id = tid + i * 256;
        int r = id >> 2, ch = id & 3;
        cpa16(st + r * ROWB + ch * 16,       Ab + (size_t)r * K + kb * 32 + ch * 8);
        cpa16(st + OPB + r * ROWB + ch * 16, Bb + (size_t)r * K + kb * 32 + ch * 8);
    }
}

template<int EPI>
__global__ void __launch_bounds__(256, 2)
k_tgemm(const __nv_bfloat16* __restrict__ A, const __nv_bfloat16* __restrict__ Bt,
        float* __restrict__ C, __nv_bfloat16* __restrict__ Cb, int M, int N, int K) {
    extern __shared__ char smem[];
    uint32_t sb = smem_u32(smem);
    int tid = threadIdx.x;
    int lane = tid & 31, w = tid >> 5;
    int wm = w >> 1, wn = w & 1;
    int m0 = blockIdx.x * 128, n0 = blockIdx.y * 128;
    const __nv_bfloat16* Ab = A + (size_t)m0 * K;
    const __nv_bfloat16* Bb = Bt + (size_t)n0 * K;

    float acc[2][8][4];
#pragma unroll
    for (int i = 0; i < 2; i++)
#pragma unroll
        for (int j = 0; j < 8; j++)
#pragma unroll
            for (int q = 0; q < 4; q++) acc[i][j][q] = 0.f;

    int nk = K >> 5;
#pragma unroll
    for (int s = 0; s < GSTG - 1; s++) {
        g_load_stage(sb + s * STGB, Ab, Bb, K, s, tid);
        CP_COMMIT();
    }

    uint32_t aoff = (uint32_t)((wm * 32 + (lane & 15)) * ROWB + (lane >> 4) * 16);
    uint32_t boff = (uint32_t)(OPB + (wn * 64 + (lane & 7) + ((lane >> 4) & 1) * 8) * ROWB +
                               ((lane >> 3) & 1) * 16);

    for (int kb = 0; kb < nk; kb++) {
        uint32_t st = sb + (kb % GSTG) * STGB;
        CP_WAIT1();
        __syncthreads();
        if (kb + GSTG - 1 < nk)
            g_load_stage(sb + ((kb + GSTG - 1) % GSTG) * STGB, Ab, Bb, K, kb + GSTG - 1, tid);
        CP_COMMIT();

#pragma unroll
        for (int ks = 0; ks < 2; ks++) {
            uint32_t a[2][4], b[4][4];
#pragma unroll
            for (int mt = 0; mt < 2; mt++)
                ldsm4(a[mt][0], a[mt][1], a[mt][2], a[mt][3],
                      st + aoff + mt * 16 * ROWB + ks * 32);
#pragma unroll
            for (int p = 0; p < 4; p++)
                ldsm4(b[p][0], b[p][1], b[p][2], b[p][3],
                      st + boff + p * 16 * ROWB + ks * 32);
#pragma unroll
            for (int mt = 0; mt < 2; mt++)
#pragma unroll
                for (int p = 0; p < 4; p++) {
                    mma16816(acc[mt][2 * p],     a[mt], &b[p][0]);
                    mma16816(acc[mt][2 * p + 1], a[mt], &b[p][2]);
                }
        }
    }

    if constexpr (EPI == 0) {
#pragma unroll
        for (int mt = 0; mt < 2; mt++) {
            int r0 = m0 + wm * 32 + mt * 16 + (lane >> 2);
#pragma unroll
            for (int nt = 0; nt < 8; nt++) {
                int c = n0 + wn * 64 + nt * 8 + (lane & 3) * 2;
                *(float2*)(C + (size_t)r0 * N + c)       = make_float2(acc[mt][nt][0], acc[mt][nt][1]);
                *(float2*)(C + (size_t)(r0 + 8) * N + c) = make_float2(acc[mt][nt][2], acc[mt][nt][3]);
            }
        }
    } else if constexpr (EPI == 1) {
#pragma unroll
        for (int mt = 0; mt < 2; mt++) {
            int r0 = m0 + wm * 32 + mt * 16 + (lane >> 2);
#pragma unroll
            for (int nt = 0; nt < 8; nt++) {
                int c = n0 + wn * 64 + nt * 8 + (lane & 3) * 2;
                __nv_bfloat162 v0 = __floats2bfloat162_rn(acc[mt][nt][0], acc[mt][nt][1]);
                __nv_bfloat162 v1 = __floats2bfloat162_rn(acc[mt][nt][2], acc[mt][nt][3]);
                *(__nv_bfloat162*)(Cb + (size_t)r0 * N + c)       = v0;
                *(__nv_bfloat162*)(Cb + (size_t)(r0 + 8) * N + c) = v1;
            }
        }
    } else {
        // fused online-softmax CE partials over this tile's 64-col chunks
        int q = lane >> 2, ln4 = lane & 3;
        int cbase = n0 + wn * 64;
        int chunk = cbase >> 6;
#pragma unroll
        for (int mt = 0; mt < 2; mt++) {
#pragma unroll
            for (int half = 0; half < 2; half++) {
                int r = m0 + wm * 32 + mt * 16 + half * 8 + q;
                int tr = g_tgt[r];
                float vmax = -3.4e38f; int vidx = 0;
#pragma unroll
                for (int nt = 0; nt < 8; nt++) {
#pragma unroll
                    for (int e = 0; e < 2; e++) {
                        float v = acc[mt][nt][half * 2 + e];
                        int c = cbase + nt * 8 + ln4 * 2 + e;
                        if (v > vmax) { vmax = v; vidx = c; }
                        if (c == tr) g_tgtlog[r] = v;
                    }
                }
#pragma unroll
                for (int o = 1; o < 4; o <<= 1) {
                    float v2 = __shfl_xor_sync(0xffffffffu, vmax, o);
                    int   i2 = __shfl_xor_sync(0xffffffffu, vidx, o);
                    if (v2 > vmax || (v2 == vmax && i2 < vidx)) { vmax = v2; vidx = i2; }
                }
                float s = 0.f;
#pragma unroll
                for (int nt = 0; nt < 8; nt++)
#pragma unroll
                    for (int e = 0; e < 2; e++)
                        s += expf(acc[mt][nt][half * 2 + e] - vmax);
#pragma unroll
                for (int o = 1; o < 4; o <<= 1)
                    s += __shfl_xor_sync(0xffffffffu, s, o);
                if (ln4 == 0) {
                    size_t pi = (size_t)r * NCH + chunk;
                    g_pmax[pi] = vmax;
                    g_psum[pi] = s;
                    g_pidx[pi] = vidx;
                }
            }
        }
    }
}

// ---------------- rope + gather ----------------
__global__ void k_ropegather() {
    int r  = blockIdx.x;
    int kk = r % 17;
    int ai = r / 17;
    int crow = (kk == 0) ? ai : ((kk == 1) ? (NAI + ai) : 512);
    int pos = (kk == 0) ? g_ctxpos[ai] : (g_anchor[ai] + kk - 1);
    const float* qs = g_qkvc + (size_t)crow * (3 * DD);
    const float* ks = qs + DD;
    const float* vs = qs + 2 * DD;
    float* qo = g_pq + (size_t)r * DD;
    float* ko = g_pk + (size_t)r * DD;
    float* vo = g_pv + (size_t)r * DD;
    for (int p = threadIdx.x; p < HH * 64; p += blockDim.x) {
        int h = p >> 6, d = p & 63;
        float inv = expf(-(float)d * 0.14391156965722198f);
        float ang = (float)pos * inv;
        float s, c;
        sincosf(ang, &s, &c);
        int c1 = h * HD + d, c2 = c1 + 64;
        float k1 = ks[c1], k2 = ks[c2];
        ko[c1] = k1 * c - k2 * s;
        ko[c2] = k2 * c + k1 * s;
        float q1 = qs[c1], q2 = qs[c2];
        qo[c1] = q1 * c - q2 * s;
        qo[c2] = q2 * c + q1 * s;
        vo[c1] = vs[c1];
        vo[c2] = vs[c2];
    }
}

// ---------------- attention ----------------
__global__ void __launch_bounds__(288) k_attn() {
    int g = blockIdx.x;
    int h  = g & 15;
    int na = (g >> 4) & 127;
    int b  = g >> 11;
    int base = (b * NA + na) * 17;
    __shared__ float sk[17][HD], sv[17][HD], sq[BSQ][HD], sw[BSQ][18];
    int tid = threadIdx.x;
    for (int i = tid; i < 17 * HD; i += 288) {
        int r = i >> 7, c = i & 127;
        size_t off = (size_t)(base + r) * DD + h * HD + c;
        sk[r][c] = g_pk[off];
        sv[r][c] = g_pv[off];
    }
    for (int i = tid; i < BSQ * HD; i += 288) {
        int r = i >> 7, c = i & 127;
        sq[r][c] = g_pq[(size_t)(base + 1 + r) * DD + h * HD + c];
    }
    __syncthreads();
    if (tid < BSQ * 17) {
        int j = tid / 17, kk = tid % 17;
        float d = 0.f;
#pragma unroll 8
        for (int c = 0; c < HD; c++) d += sq[j][c] * sk[kk][c];
        sw[j][kk] = d * 0.08838834764831845f;
    }
    __syncthreads();
    if (tid < BSQ) {
        float m = -3.4e38f;
        for (int kk = 0; kk < 17; kk++) m = fmaxf(m, sw[tid][kk]);
        float s = 0.f;
        for (int kk = 0; kk < 17; kk++) { float e = expf(sw[tid][kk] - m); sw[tid][kk] = e; s += e; }
        float invs = 1.f / s;
        for (int kk = 0; kk < 17; kk++) sw[tid][kk] *= invs;
    }
    __syncthreads();
    for (int i = tid; i < BSQ * HD; i += 288) {
        int j = i >> 7, c = i & 127;
        float o = 0.f;
#pragma unroll
        for (int kk = 0; kk < 17; kk++) o += sw[j][kk] * sv[kk][c];
        g_attno_bf[(size_t)(b * 2048 + na * BSQ + j) * DD + h * HD + c] = __float2bfloat16(o);
    }
}

// ---------------- residual / swiglu (vectorized) ----------------
__global__ void k_resid(float* __restrict__ x, const float* __restrict__ o, int useKeep) {
    size_t n4 = (size_t)TT * DD / 4;
    for (size_t i = (size_t)blockIdx.x * blockDim.x + threadIdx.x; i < n4;
         i += (size_t)gridDim.x * blockDim.x) {
        int t = (int)(i >> 9);          // DD/4 = 512 float4 per row
        float m = useKeep ? (float)g_keep[t >> 4] : 1.f;
        float4 a = ((float4*)x)[i];
        float4 b = ((const float4*)o)[i];
        a.x += m * b.x; a.y += m * b.y; a.z += m * b.z; a.w += m * b.w;
        ((float4*)x)[i] = a;
    }
}
__global__ void k_swiglu(const __nv_bfloat16* __restrict__ ffc,
                         __nv_bfloat16* __restrict__ out) {
    size_t n8 = (size_t)TT * DFF / 8;
    for (size_t i = (size_t)blockIdx.x * blockDim.x + threadIdx.x; i < n8;
         i += (size_t)gridDim.x * blockDim.x) {
        size_t base = i * 8;
        size_t r = base >> 13, c = base & (DFF - 1);
        const __nv_bfloat162* gp = (const __nv_bfloat162*)(ffc + r * (2 * DFF) + c);
        const __nv_bfloat162* up = (const __nv_bfloat162*)(ffc + r * (2 * DFF) + DFF + c);
        __align__(16) __nv_bfloat16 tmp[8];
#pragma unroll
        for (int j = 0; j < 4; j++) {
            float2 g = __bfloat1622float2(gp[j]);
            float2 u = __bfloat1622float2(up[j]);
            float s0 = g.x / (1.f + expf(-g.x));
            float s1 = g.y / (1.f + expf(-g.y));
            tmp[2 * j]     = __float2bfloat16(s0 * u.x);
            tmp[2 * j + 1] = __float2bfloat16(s1 * u.y);
        }
        *(uint4*)(out + base) = *(uint4*)tmp;
    }
}

// ---------------- final CE reduce (warp per row over 500 chunks) ----------------
__global__ void k_loss2() {
    int row = blockIdx.x * 8 + (threadIdx.x >> 5);
    int lane = threadIdx.x & 31;
    float M = -3.4e38f, S = 0.f;
    int AI = 0x7fffffff;
    for (int ch = lane; ch < NCH; ch += 32) {
        size_t pi = (size_t)row * NCH + ch;
        float m = g_pmax[pi];
        float s = g_psum[pi];
        int ix = g_pidx[pi];
        if (m > M) { S = S * expf(M - m) + s; M = m; AI = ix; }
        else       { S += s * expf(m - M); }   // ties keep earlier (lower) index
    }
#pragma unroll
    for (int o = 16; o > 0; o >>= 1) {
        float M2 = __shfl_xor_sync(0xffffffffu, M, o);
        float S2 = __shfl_xor_sync(0xffffffffu, S, o);
        int   A2 = __shfl_xor_sync(0xffffffffu, AI, o);
        if (M2 > M) { S = S * expf(M - M2) + S2; M = M2; AI = A2; }
        else if (M2 == M) { S += S2; if (A2 < AI) AI = A2; }
        else { S += S2 * expf(M2 - M); }
    }
    if (lane == 0) {
        float w = g_wgt[row];
        float logZ = M + logf(S);
        float lp = g_tgtlog[row] - logZ;
        g_tokl[row] = w * (-lp);
        g_tokw[row] = w;
        g_toka[row] = (AI == g_tgt[row] && w > 0.5f) ? 1.f : 0.f;
    }
}

__global__ void k_final(float* __restrict__ out) {
    __shared__ float s1[256], s2[256], s3[256];
    int tid = threadIdx.x;
    float a = 0.f, b = 0.f, c = 0.f;
    for (int t = tid; t < TT; t += 256) { a += g_tokl[t]; b += g_tokw[t]; c += g_toka[t]; }
    s1[tid] = a; s2[tid] = b; s3[tid] = c; __syncthreads();
    for (int s = 128; s > 0; s >>= 1) {
        if (tid < s) { s1[tid] += s1[tid + s]; s2[tid] += s2[tid + s]; s3[tid] += s3[tid + s]; }
        __syncthreads();
    }
    if (tid == 0) {
        float denom = s2[0] + 1e-6f;
        out[0] = s1[0] / denom;
        out[1] = s3[0] / denom;
    }
}

// ---------------- driver ----------------
extern "C" void kernel_launch(void* const* d_in, const int* in_sizes, int n_in,
                              void* d_out, int out_size) {
    const int*   input_ids     = (const int*)  d_in[0];
    const float* hidden_states = (const float*)d_in[1];
    const float* loss_mask     = (const float*)d_in[2];
    const float* rand_vals     = (const float*)d_in[3];
    const float* embed_table   = (const float*)d_in[4];
    const float* lm_head_w     = (const float*)d_in[5];
    const float* wq            = (const float*)d_in[6];
    const float* wk            = (const float*)d_in[7];
    const float* wv            = (const float*)d_in[8];
    const float* wo            = (const float*)d_in[9];
    const float* w_gate        = (const float*)d_in[10];
    const float* w_up          = (const float*)d_in[11];
    const float* w_down        = (const float*)d_in[12];
    const float* norm_attn     = (const float*)d_in[13];
    const float* norm_mlp      = (const float*)d_in[14];
    const float* norm_out      = (const float*)d_in[15];
    const float* norm_chs      = (const float*)d_in[16];
    float* out = (float*)d_out;

    static int smem_set = 0;
    if (!smem_set) {
        cudaFuncSetAttribute((const void*)k_tgemm<0>, cudaFuncAttributeMaxDynamicSharedMemorySize, GSMEM);
        cudaFuncSetAttribute((const void*)k_tgemm<1>, cudaFuncAttributeMaxDynamicSharedMemorySize, GSMEM);
        cudaFuncSetAttribute((const void*)k_tgemm<2>, cudaFuncAttributeMaxDynamicSharedMemorySize, GSMEM);
        smem_set = 1;
    }

    float *px, *pqkvc, *po;
    __nv_bfloat16 *pkvin, *pattno, *ph, *pffc, *pff1p;
    __nv_bfloat16 *pwqkvT, *pwoT, *pwguT, *pwdT, *plmb;
    cudaGetSymbolAddress((void**)&px,     g_x);
    cudaGetSymbolAddress((void**)&pqkvc,  g_qkvc);
    cudaGetSymbolAddress((void**)&po,     g_o);
    cudaGetSymbolAddress((void**)&pkvin,  g_kvin_bf);
    cudaGetSymbolAddress((void**)&pattno, g_attno_bf);
    cudaGetSymbolAddress((void**)&ph,     g_h_bf);
    cudaGetSymbolAddress((void**)&pffc,   g_ffc_bf);
    cudaGetSymbolAddress((void**)&pff1p,  g_ff1p_bf);
    cudaGetSymbolAddress((void**)&pwqkvT, g_wqkvT);
    cudaGetSymbolAddress((void**)&pwoT,   g_woT);
    cudaGetSymbolAddress((void**)&pwguT,  g_wguT);
    cudaGetSymbolAddress((void**)&pwdT,   g_wdT);
    cudaGetSymbolAddress((void**)&plmb,   g_lmb);

    // weight prep
    k_convT<<<dim3(DD / 64, DD / 64), 256>>>(wq, pwqkvT, DD, DD);
    k_convT<<<dim3(DD / 64, DD / 64), 256>>>(wk, pwqkvT + (size_t)DD * DD, DD, DD);
    k_convT<<<dim3(DD / 64, DD / 64), 256>>>(wv, pwqkvT + (size_t)2 * DD * DD, DD, DD);
    k_convT<<<dim3(DD / 64, DD / 64), 256>>>(wo, pwoT, DD, DD);
    k_convT<<<dim3(DFF / 64, DD / 64), 256>>>(w_gate, pwguT, DD, DFF);
    k_convT<<<dim3(DFF / 64, DD / 64), 256>>>(w_up, pwguT + (size_t)DFF * DD, DD, DFF);
    k_convT<<<dim3(DD / 64, DFF / 64), 256>>>(w_down, pwdT, DFF, DD);
    k_conv<<<4096, 256>>>(lm_head_w, plmb, (size_t)VV * DD / 8);

    k_rank<<<dim3(16, BB), 256>>>(rand_vals, loss_mask);
    k_compact<<<BB, 256>>>(input_ids);
    k_prep<<<TT / 256, 256>>>(input_ids, loss_mask);
    k_embed<<<TT, 256>>>(embed_table);
    k_rms_hc<<<NAI, 256>>>(hidden_states, norm_chs);
    k_rms_hq<<<NAI + 1, 256>>>(embed_table, norm_attn);
    // fused compact QKV
    k_tgemm<0><<<dim3(CQ / 128, 3 * DD / 128), 256, GSMEM>>>(pkvin, pwqkvT, pqkvc, nullptr, CQ, 3 * DD, DD);
    k_ropegather<<<KVT, 256>>>();
    k_attn<<<TT, 288>>>();
    k_tgemm<0><<<dim3(TT / 128, DD / 128), 256, GSMEM>>>(pattno, pwoT, po, nullptr, TT, DD, DD);
    k_resid<<<2048, 256>>>(px, po, 1);
    k_rms_tok_bf<<<TT, 256>>>(px, ph, norm_mlp);
    // fused gate|up -> bf16
    k_tgemm<1><<<dim3(TT / 128, 2 * DFF / 128), 256, GSMEM>>>(ph, pwguT, nullptr, pffc, TT, 2 * DFF, DD);
    k_swiglu<<<2048, 256>>>(pffc, pff1p);
    k_tgemm<0><<<dim3(TT / 128, DD / 128), 256, GSMEM>>>(pff1p, pwdT, po, nullptr, TT, DD, DFF);
    k_resid<<<2048, 256>>>(px, po, 0);
    k_rms_tok_bf<<<TT, 256>>>(px, ph, norm_out);
    // lm head with fused softmax-CE epilogue (no logits materialized)
    k_tgemm<2><<<dim3(TT / 128, VV / 128), 256, GSMEM>>>(ph, plmb, nullptr, nullptr, TT, VV, DD);
    k_loss2<<<TT / 8, 256>>>();
    k_final<<<1, 256>>>(out);
}